// round 14
// baseline (speedup 1.0000x reference)
#include <cuda_runtime.h>
#include <cuda_fp16.h>
#include <cstdint>
#include <math.h>

// ---------------------------------------------------------------------------
// Problem constants
// ---------------------------------------------------------------------------
#define BATCH 8
#define SEQ   512
#define DMODEL 512
#define NHEAD 8
#define DHEAD 64
#define NLAYER 4
#define DFF   2048
#define VOCAB 32000
#define MROWS (BATCH*SEQ)   // 4096

__device__ __forceinline__ uint32_t smem_u32(const void* p) {
    uint32_t a;
    asm("{ .reg .u64 t; cvta.to.shared.u64 t, %1; cvt.u32.u64 %0, t; }" : "=r"(a) : "l"(p));
    return a;
}
__device__ __forceinline__ void cp16(uint32_t s, const void* g) {
    asm volatile("cp.async.cg.shared.global [%0], [%1], 16;" :: "r"(s), "l"(g));
}
#define CP_COMMIT() asm volatile("cp.async.commit_group;" ::: "memory")
template<int N> __device__ __forceinline__ void cp_wait() {
    asm volatile("cp.async.wait_group %0;" :: "n"(N) : "memory");
}
__device__ __forceinline__ void ldm_x4(uint32_t* r, uint32_t addr) {
    asm volatile("ldmatrix.sync.aligned.m8n8.x4.shared.b16 {%0,%1,%2,%3}, [%4];"
        : "=r"(r[0]), "=r"(r[1]), "=r"(r[2]), "=r"(r[3]) : "r"(addr));
}
__device__ __forceinline__ void ldm_x4_t(uint32_t* r, uint32_t addr) {
    asm volatile("ldmatrix.sync.aligned.m8n8.x4.trans.shared.b16 {%0,%1,%2,%3}, [%4];"
        : "=r"(r[0]), "=r"(r[1]), "=r"(r[2]), "=r"(r[3]) : "r"(addr));
}
__device__ __forceinline__ void mma_f16(float* c, const uint32_t* a, const uint32_t* b) {
    asm volatile(
        "mma.sync.aligned.m16n8k16.row.col.f32.f16.f16.f32 "
        "{%0,%1,%2,%3}, {%4,%5,%6,%7}, {%8,%9}, {%0,%1,%2,%3};"
        : "+f"(c[0]), "+f"(c[1]), "+f"(c[2]), "+f"(c[3])
        : "r"(a[0]), "r"(a[1]), "r"(a[2]), "r"(a[3]), "r"(b[0]), "r"(b[1]));
}

// ---------------------------------------------------------------------------
// Scratch (device globals; no allocation allowed)
// ---------------------------------------------------------------------------
__device__ __align__(16) float  g_x   [MROWS*DMODEL];
__device__ __align__(16) float  g_xd  [MROWS*DMODEL];
__device__ __align__(16) __half g_x2  [MROWS*DMODEL];
__device__ __align__(16) __half g_x2d [MROWS*DMODEL];
__device__ __align__(16) __half g_qb  [MROWS*DMODEL];
__device__ __align__(16) __half g_ctx [MROWS*DMODEL];
__device__ __align__(16) __half g_ctxd[MROWS*DMODEL];
__device__ __align__(16) __half g_enc [MROWS*DMODEL];
__device__ __align__(16) __half g_h   [MROWS*DFF];
__device__ __align__(16) __half g_qkv [MROWS*3*DMODEL];
__device__ __align__(16) __half g_qkvd[MROWS*3*DMODEL];
__device__ __align__(16) __half g_kvb [NLAYER][MROWS*2*DMODEL];

// converted-weight arena (fp16)
#define OFF_ENC_ATTN 0
#define OFF_ENC_W1   (OFF_ENC_ATTN + NLAYER*4*DMODEL*DMODEL)
#define OFF_ENC_W2   (OFF_ENC_W1   + NLAYER*DFF*DMODEL)
#define OFF_DEC_ATTN (OFF_ENC_W2   + NLAYER*DMODEL*DFF)
#define OFF_DEC_W1   (OFF_DEC_ATTN + NLAYER*8*DMODEL*DMODEL)
#define OFF_DEC_W2   (OFF_DEC_W1   + NLAYER*DFF*DMODEL)
#define OFF_EMB      (OFF_DEC_W2   + NLAYER*DMODEL*DFF)
#define W_TOTAL      (OFF_EMB      + VOCAB*DMODEL)
__device__ __align__(16) __half g_w[W_TOTAL];

// ---------------------------------------------------------------------------
// fp32 -> fp16 conversion
// ---------------------------------------------------------------------------
__global__ void cvt_kernel(const float* __restrict__ in, __half* __restrict__ out, int n) {
    int i = (blockIdx.x*blockDim.x + threadIdx.x)*8;
    if (i < n) {
        float4 a = *(const float4*)(in + i);
        float4 b = *(const float4*)(in + i + 4);
        __half2 h0 = __floats2half2_rn(a.x, a.y);
        __half2 h1 = __floats2half2_rn(a.z, a.w);
        __half2 h2 = __floats2half2_rn(b.x, b.y);
        __half2 h3 = __floats2half2_rn(b.z, b.w);
        uint4 o;
        o.x = *(uint32_t*)&h0; o.y = *(uint32_t*)&h1;
        o.z = *(uint32_t*)&h2; o.w = *(uint32_t*)&h3;
        *(uint4*)(out + i) = o;
    }
}

// ---------------------------------------------------------------------------
// Embedding + sinusoidal positional encoding (residual stream, fp32)
// ---------------------------------------------------------------------------
__global__ void embed_kernel(const int* __restrict__ tok,
                             const float* __restrict__ emb,
                             float* __restrict__ y) {
    int row = blockIdx.x;
    int s   = row % SEQ;
    int t   = tok[row];
    const float scale = 22.62741699796952f;
    const float c0 = -9.210340371976184f / (float)DMODEL;
    int tid = threadIdx.x;
    #pragma unroll
    for (int i = 0; i < 4; i++) {
        int d = tid + i*128;
        float e = (t == 0) ? 0.f : emb[(size_t)t*DMODEL + d];
        int half = d >> 1;
        float div = expf((float)(2*half) * c0);
        float ang = (float)s * div;
        float pe = (d & 1) ? cosf(ang) : sinf(ang);
        y[(size_t)row*DMODEL + d] = e*scale + pe;
    }
}

// ---------------------------------------------------------------------------
// LayerNorm, warp-per-row (8 rows / 256-thread block).
// ---------------------------------------------------------------------------
__global__ __launch_bounds__(256)
void ln_kernel(const float* __restrict__ x,
               const float* __restrict__ g,
               const float* __restrict__ b,
               __half* __restrict__ y) {
    int row  = blockIdx.x*8 + (threadIdx.x >> 5);
    int lane = threadIdx.x & 31;
    const float* xr = x + (size_t)row*DMODEL;
    float4 v[4];
    float s = 0.f;
    #pragma unroll
    for (int c = 0; c < 4; c++) {
        v[c] = *(const float4*)(xr + lane*4 + c*128);
        s += (v[c].x + v[c].y) + (v[c].z + v[c].w);
    }
    #pragma unroll
    for (int o = 16; o > 0; o >>= 1) s += __shfl_xor_sync(0xffffffffu, s, o);
    float mean = s * (1.f/(float)DMODEL);
    float vs = 0.f;
    #pragma unroll
    for (int c = 0; c < 4; c++) {
        float d0 = v[c].x-mean, d1 = v[c].y-mean, d2 = v[c].z-mean, d3 = v[c].w-mean;
        vs += d0*d0 + d1*d1 + d2*d2 + d3*d3;
    }
    #pragma unroll
    for (int o = 16; o > 0; o >>= 1) vs += __shfl_xor_sync(0xffffffffu, vs, o);
    float inv = rsqrtf(vs * (1.f/(float)DMODEL) + 1e-5f);
    #pragma unroll
    for (int c = 0; c < 4; c++) {
        int d = lane*4 + c*128;
        float4 gv = *(const float4*)(g + d);
        float4 bv = *(const float4*)(b + d);
        float r0 = (v[c].x-mean)*inv*gv.x + bv.x;
        float r1 = (v[c].y-mean)*inv*gv.y + bv.y;
        float r2 = (v[c].z-mean)*inv*gv.z + bv.z;
        float r3 = (v[c].w-mean)*inv*gv.w + bv.w;
        __half2 h0 = __floats2half2_rn(r0, r1);
        __half2 h1 = __floats2half2_rn(r2, r3);
        uint2 o; o.x = *(uint32_t*)&h0; o.y = *(uint32_t*)&h1;
        *(uint2*)(y + (size_t)row*DMODEL + d) = o;
    }
}

// ---------------------------------------------------------------------------
// fp16 mma.sync GEMM, CTA 128x128x32 (wide-N shapes).
// ---------------------------------------------------------------------------
#define TSTR 40
#define TILE_HALFS (128*TSTR)
#define STAGE_HALFS (2*TILE_HALFS)
#define GEMM_SMEM (3*STAGE_HALFS*2)

template<bool RELU, bool RES, bool BIAS, bool OHALF>
__global__ __launch_bounds__(256, 2)
void gemm_mma(const __half* __restrict__ A, const __half* __restrict__ W,
              const float* __restrict__ bias, const float* __restrict__ res,
              void* __restrict__ Cv, int M, int N, int K) {
    extern __shared__ __half smh[];
    int t = threadIdx.x, lane = t & 31, wid = t >> 5;
    int wm = (wid & 1) * 64;
    int wn = (wid >> 1) * 32;
    int r4 = lane >> 2, l4 = lane & 3;

    const __half* Ab = A + (size_t)blockIdx.y*128*K;
    const __half* Wb = W + (size_t)blockIdx.x*128*K;
    uint32_t sbase = smem_u32(smh);

    float acc[4][4][4];
    #pragma unroll
    for (int i = 0; i < 4; i++)
        #pragma unroll
        for (int j = 0; j < 4; j++)
            #pragma unroll
            for (int c = 0; c < 4; c++) acc[i][j][c] = 0.f;

    int NK = K >> 5;

    auto issue = [&](int it, int buf) {
        uint32_t base = sbase + (uint32_t)buf*STAGE_HALFS*2;
        int k0 = it*32;
        #pragma unroll
        for (int i = 0; i < 2; i++) {
            int idx = t + i*256, r = idx >> 2, ch = idx & 3;
            uint32_t off = (uint32_t)(r*TSTR + ch*8)*2;
            cp16(base + off,                  Ab + (size_t)r*K + k0 + ch*8);
            cp16(base + TILE_HALFS*2 + off,   Wb + (size_t)r*K + k0 + ch*8);
        }
        CP_COMMIT();
    };

    issue(0, 0);
    issue(1, 1);

    int a_row = (lane & 15);
    int a_kh8 = (lane >> 4) * 8;
    int b_row = (lane & 7) + ((lane >> 4) & 1) * 8;
    int b_kh8 = ((lane >> 3) & 1) * 8;

    for (int it = 0; it < NK; it++) {
        if (it + 1 < NK) cp_wait<1>(); else cp_wait<0>();
        __syncthreads();
        if (it + 2 < NK) issue(it + 2, (it + 2) % 3);
        uint32_t sA = sbase + (uint32_t)(it % 3)*STAGE_HALFS*2;
        uint32_t sB = sA + TILE_HALFS*2;
        #pragma unroll
        for (int kh = 0; kh < 2; kh++) {
            uint32_t af[4][4], bf[2][4];
            #pragma unroll
            for (int mi = 0; mi < 4; mi++)
                ldm_x4(af[mi], sA + (uint32_t)((wm + mi*16 + a_row)*TSTR + kh*16 + a_kh8)*2);
            #pragma unroll
            for (int nb = 0; nb < 2; nb++)
                ldm_x4(bf[nb], sB + (uint32_t)((wn + nb*16 + b_row)*TSTR + kh*16 + b_kh8)*2);
            #pragma unroll
            for (int mi = 0; mi < 4; mi++) {
                #pragma unroll
                for (int ni = 0; ni < 4; ni++)
                    mma_f16(acc[mi][ni], af[mi], bf[ni >> 1] + (ni & 1)*2);
            }
        }
    }

    int gm = blockIdx.y*128 + wm;
    int gn = blockIdx.x*128 + wn;
    #pragma unroll
    for (int mi = 0; mi < 4; mi++) {
        #pragma unroll
        for (int ni = 0; ni < 4; ni++) {
            int row = gm + mi*16 + r4;
            int col = gn + ni*8 + l4*2;
            float2 v0 = make_float2(acc[mi][ni][0], acc[mi][ni][1]);
            float2 v1 = make_float2(acc[mi][ni][2], acc[mi][ni][3]);
            if (BIAS) {
                float2 bv = *(const float2*)(bias + col);
                v0.x += bv.x; v0.y += bv.y; v1.x += bv.x; v1.y += bv.y;
            }
            if (RELU) {
                v0.x = fmaxf(v0.x, 0.f); v0.y = fmaxf(v0.y, 0.f);
                v1.x = fmaxf(v1.x, 0.f); v1.y = fmaxf(v1.y, 0.f);
            }
            if (RES) {
                float2 r0 = *(const float2*)(res + (size_t)row*N + col);
                float2 r1 = *(const float2*)(res + (size_t)(row+8)*N + col);
                v0.x += r0.x; v0.y += r0.y; v1.x += r1.x; v1.y += r1.y;
            }
            if (OHALF) {
                __half* C = (__half*)Cv;
                *(__half2*)(C + (size_t)row*N + col)     = __floats2half2_rn(v0.x, v0.y);
                *(__half2*)(C + (size_t)(row+8)*N + col) = __floats2half2_rn(v1.x, v1.y);
            } else {
                float* C = (float*)Cv;
                *(float2*)(C + (size_t)row*N + col)     = v0;
                *(float2*)(C + (size_t)(row+8)*N + col) = v1;
            }
        }
    }
}

// ---------------------------------------------------------------------------
// fp16 mma.sync GEMM, CTA 64x128x32 (narrow-N shapes).
// ---------------------------------------------------------------------------
#define A64_HALFS (64*TSTR)
#define S64_HALFS (A64_HALFS + TILE_HALFS)
#define GEMM64_SMEM (3*S64_HALFS*2)

template<bool RELU, bool RES, bool BIAS, bool OHALF>
__global__ __launch_bounds__(256)
void gemm_mma64(const __half* __restrict__ A, const __half* __restrict__ W,
                const float* __restrict__ bias, const float* __restrict__ res,
                void* __restrict__ Cv, int M, int N, int K) {
    extern __shared__ __half smh[];
    int t = threadIdx.x, lane = t & 31, wid = t >> 5;
    int wm = (wid & 1) * 32;
    int wn = (wid >> 1) * 32;
    int r4 = lane >> 2, l4 = lane & 3;

    const __half* Ab = A + (size_t)blockIdx.y*64*K;
    const __half* Wb = W + (size_t)blockIdx.x*128*K;
    uint32_t sbase = smem_u32(smh);

    float acc[2][4][4];
    #pragma unroll
    for (int i = 0; i < 2; i++)
        #pragma unroll
        for (int j = 0; j < 4; j++)
            #pragma unroll
            for (int c = 0; c < 4; c++) acc[i][j][c] = 0.f;

    int NK = K >> 5;

    auto issue = [&](int it, int buf) {
        uint32_t base = sbase + (uint32_t)buf*S64_HALFS*2;
        int k0 = it*32;
        {
            int r = t >> 2, ch = t & 3;
            cp16(base + (uint32_t)(r*TSTR + ch*8)*2, Ab + (size_t)r*K + k0 + ch*8);
        }
        #pragma unroll
        for (int i = 0; i < 2; i++) {
            int idx = t + i*256, r = idx >> 2, ch = idx & 3;
            cp16(base + A64_HALFS*2 + (uint32_t)(r*TSTR + ch*8)*2,
                 Wb + (size_t)r*K + k0 + ch*8);
        }
        CP_COMMIT();
    };

    issue(0, 0);
    issue(1, 1);

    int a_row = (lane & 15);
    int a_kh8 = (lane >> 4) * 8;
    int b_row = (lane & 7) + ((lane >> 4) & 1) * 8;
    int b_kh8 = ((lane >> 3) & 1) * 8;

    for (int it = 0; it < NK; it++) {
        if (it + 1 < NK) cp_wait<1>(); else cp_wait<0>();
        __syncthreads();
        if (it + 2 < NK) issue(it + 2, (it + 2) % 3);
        uint32_t sA = sbase + (uint32_t)(it % 3)*S64_HALFS*2;
        uint32_t sB = sA + A64_HALFS*2;
        #pragma unroll
        for (int kh = 0; kh < 2; kh++) {
            uint32_t af[2][4], bf[2][4];
            #pragma unroll
            for (int mi = 0; mi < 2; mi++)
                ldm_x4(af[mi], sA + (uint32_t)((wm + mi*16 + a_row)*TSTR + kh*16 + a_kh8)*2);
            #pragma unroll
            for (int nb = 0; nb < 2; nb++)
                ldm_x4(bf[nb], sB + (uint32_t)((wn + nb*16 + b_row)*TSTR + kh*16 + b_kh8)*2);
            #pragma unroll
            for (int mi = 0; mi < 2; mi++) {
                #pragma unroll
                for (int ni = 0; ni < 4; ni++)
                    mma_f16(acc[mi][ni], af[mi], bf[ni >> 1] + (ni & 1)*2);
            }
        }
    }

    int gm = blockIdx.y*64 + wm;
    int gn = blockIdx.x*128 + wn;
    #pragma unroll
    for (int mi = 0; mi < 2; mi++) {
        #pragma unroll
        for (int ni = 0; ni < 4; ni++) {
            int row = gm + mi*16 + r4;
            int col = gn + ni*8 + l4*2;
            float2 v0 = make_float2(acc[mi][ni][0], acc[mi][ni][1]);
            float2 v1 = make_float2(acc[mi][ni][2], acc[mi][ni][3]);
            if (BIAS) {
                float2 bv = *(const float2*)(bias + col);
                v0.x += bv.x; v0.y += bv.y; v1.x += bv.x; v1.y += bv.y;
            }
            if (RELU) {
                v0.x = fmaxf(v0.x, 0.f); v0.y = fmaxf(v0.y, 0.f);
                v1.x = fmaxf(v1.x, 0.f); v1.y = fmaxf(v1.y, 0.f);
            }
            if (RES) {
                float2 r0 = *(const float2*)(res + (size_t)row*N + col);
                float2 r1 = *(const float2*)(res + (size_t)(row+8)*N + col);
                v0.x += r0.x; v0.y += r0.y; v1.x += r1.x; v1.y += r1.y;
            }
            if (OHALF) {
                __half* C = (__half*)Cv;
                *(__half2*)(C + (size_t)row*N + col)     = __floats2half2_rn(v0.x, v0.y);
                *(__half2*)(C + (size_t)(row+8)*N + col) = __floats2half2_rn(v1.x, v1.y);
            } else {
                float* C = (float*)Cv;
                *(float2*)(C + (size_t)row*N + col)     = v0;
                *(float2*)(C + (size_t)(row+8)*N + col) = v1;
            }
        }
    }
}

// ---------------------------------------------------------------------------
// Flash attention (R10 configuration): q-tile 64, 128 threads (4 warps),
// cp.async double-buffered K/V. S-phase warp-local stats + causal subtile
// skip; PV keeps warp-private d-slices (V trans-loaded once per warp).
// ---------------------------------------------------------------------------
#define ASS 72
#define ATILE (64*ASS)
#define FH_TOT (6*ATILE)
#define ATTN_SMEM (FH_TOT*2 + 2816)

__global__ __launch_bounds__(128)
void attn_mma(const __half* __restrict__ Qp, int qstride,
              const __half* __restrict__ Kp, const __half* __restrict__ Vp, int kvstride,
              __half* __restrict__ Op,
              const int* __restrict__ mtok, int causal) {
    extern __shared__ __half smh[];
    __half* Ps = smh + 5*ATILE;
    float* alphas = (float*)(smh + FH_TOT);
    float* linv   = alphas + 64;
    uint32_t* maskv = (uint32_t*)(linv + 64);

    int t = threadIdx.x, lane = t & 31, w = t >> 5;
    int r4 = lane >> 2, l4 = lane & 3;
    int q0 = blockIdx.x * 64, h = blockIdx.y, b = blockIdx.z;
    const __half* Qb = Qp + (size_t)b*SEQ*qstride  + h*DHEAD;
    const __half* Kb = Kp + (size_t)b*SEQ*kvstride + h*DHEAD;
    const __half* Vb = Vp + (size_t)b*SEQ*kvstride + h*DHEAD;

    uint32_t qs_b = smem_u32(smh);
    uint32_t ps_b = smem_u32(Ps);

    int a_row = (lane & 15);
    int a_k8  = (lane >> 4) * 8;
    int b_row = (lane & 7) + ((lane >> 4) & 1) * 8;
    int b_k8  = ((lane >> 3) & 1) * 8;
    int v_s   = (lane & 7) + ((lane >> 4) & 1) * 8;
    int v_d8  = ((lane >> 3) & 1) * 8;

    int qcnk = q0 >> 6;
    int nchunks = causal ? (qcnk + 1) : (SEQ/64);
    int m0 = w*16;

    auto issue_kv = [&](int kt, int buf) {
        uint32_t kbase = qs_b + (uint32_t)(1 + buf)*ATILE*2;
        uint32_t vbase = qs_b + (uint32_t)(3 + buf)*ATILE*2;
        const __half* Kc = Kb + (size_t)kt*64*kvstride;
        const __half* Vc = Vb + (size_t)kt*64*kvstride;
        #pragma unroll
        for (int i = 0; i < 4; i++) {
            int idx = t + i*128, s = idx >> 3, ch = idx & 7;
            uint32_t off = (uint32_t)(s*ASS + ch*8)*2;
            cp16(kbase + off, Kc + (size_t)s*kvstride + ch*8);
            cp16(vbase + off, Vc + (size_t)s*kvstride + ch*8);
        }
        CP_COMMIT();
    };

    #pragma unroll
    for (int i = 0; i < 4; i++) {
        int idx = t + i*128, s = idx >> 3, ch = idx & 7;
        cp16(qs_b + (uint32_t)(s*ASS + ch*8)*2, Qb + (size_t)(q0+s)*qstride + ch*8);
    }
    CP_COMMIT();
    #pragma unroll
    for (int i = 0; i < 4; i++) {
        int idx = t + i*128;
        maskv[idx] = (mtok[b*SEQ + idx] != 0);
    }
    issue_kv(0, 0);
    cp_wait<1>();
    __syncthreads();

    uint32_t qf[4][4];
    #pragma unroll
    for (int kh = 0; kh < 4; kh++)
        ldm_x4(qf[kh], qs_b + (uint32_t)((m0 + a_row)*ASS + kh*16 + a_k8)*2);

    float oacc[8][4];
    #pragma unroll
    for (int j = 0; j < 8; j++)
        #pragma unroll
        for (int c = 0; c < 4; c++) oacc[j][c] = 0.f;
    float mrA = -1e30f, mrB = -1e30f, lrA = 0.f, lrB = 0.f;
    int qA = q0 + m0 + r4, qB = qA + 8;

    for (int kt = 0; kt < nchunks; kt++) {
        cp_wait<0>();
        __syncthreads();
        if (kt + 1 < nchunks) issue_kv(kt + 1, (kt + 1) & 1);
        uint32_t ks_b = qs_b + (uint32_t)(1 + (kt & 1))*ATILE*2;
        uint32_t vs_b = qs_b + (uint32_t)(3 + (kt & 1))*ATILE*2;

        // ---- S = Q K^T (causal subtile skip: sacc stays 0 -> masked) ----
        float sacc[8][4];
        #pragma unroll
        for (int j = 0; j < 8; j++)
            #pragma unroll
            for (int c = 0; c < 4; c++) sacc[j][c] = 0.f;
        #pragma unroll
        for (int kh = 0; kh < 4; kh++) {
            #pragma unroll
            for (int nb = 0; nb < 4; nb++) {
                if (causal && kt*64 + nb*16 > q0 + m0 + 15) continue;
                uint32_t bf[4];
                ldm_x4(bf, ks_b + (uint32_t)((nb*16 + b_row)*ASS + kh*16 + b_k8)*2);
                mma_f16(sacc[nb*2],     qf[kh], bf);
                mma_f16(sacc[nb*2 + 1], qf[kh], bf + 2);
            }
        }
        // ---- mask + scale + row max ----
        bool diag = causal && (kt == qcnk);
        float mA = -1e30f, mB = -1e30f;
        #pragma unroll
        for (int j = 0; j < 8; j++) {
            int kl = j*8 + 2*l4;
            int kg = kt*64 + kl;
            bool pv0 = maskv[kg] != 0, pv1 = maskv[kg+1] != 0;
            bool a0 = pv0 && (!diag || kg   <= qA);
            bool a1 = pv1 && (!diag || kg+1 <= qA);
            bool b0 = pv0 && (!diag || kg   <= qB);
            bool b1 = pv1 && (!diag || kg+1 <= qB);
            sacc[j][0] = a0 ? sacc[j][0]*0.125f : -1e9f;
            sacc[j][1] = a1 ? sacc[j][1]*0.125f : -1e9f;
            sacc[j][2] = b0 ? sacc[j][2]*0.125f : -1e9f;
            sacc[j][3] = b1 ? sacc[j][3]*0.125f : -1e9f;
            mA = fmaxf(mA, fmaxf(sacc[j][0], sacc[j][1]));
            mB = fmaxf(mB, fmaxf(sacc[j][2], sacc[j][3]));
        }
        mA = fmaxf(mA, __shfl_xor_sync(0xffffffffu, mA, 1));
        mA = fmaxf(mA, __shfl_xor_sync(0xffffffffu, mA, 2));
        mB = fmaxf(mB, __shfl_xor_sync(0xffffffffu, mB, 1));
        mB = fmaxf(mB, __shfl_xor_sync(0xffffffffu, mB, 2));
        float mnA = fmaxf(mrA, mA), mnB = fmaxf(mrB, mB);
        float aA = __expf(mrA - mnA), aB = __expf(mrB - mnB);
        mrA = mnA; mrB = mnB;
        // ---- exp + write P (half) + row sums ----
        float lA = 0.f, lB = 0.f;
        #pragma unroll
        for (int j = 0; j < 8; j++) {
            float p0 = __expf(sacc[j][0] - mnA);
            float p1 = __expf(sacc[j][1] - mnA);
            float p2 = __expf(sacc[j][2] - mnB);
            float p3 = __expf(sacc[j][3] - mnB);
            lA += p0 + p1; lB += p2 + p3;
            *(__half2*)(Ps + (m0 + r4)*ASS     + j*8 + 2*l4) = __floats2half2_rn(p0, p1);
            *(__half2*)(Ps + (m0 + r4 + 8)*ASS + j*8 + 2*l4) = __floats2half2_rn(p2, p3);
        }
        lA += __shfl_xor_sync(0xffffffffu, lA, 1);
        lA += __shfl_xor_sync(0xffffffffu, lA, 2);
        lB += __shfl_xor_sync(0xffffffffu, lB, 1);
        lB += __shfl_xor_sync(0xffffffffu, lB, 2);
        lrA = lrA*aA + lA;
        lrB = lrB*aB + lB;
        if (l4 == 0) {
            alphas[m0 + r4]     = aA;
            alphas[m0 + r4 + 8] = aB;
            if (kt == nchunks - 1) {
                linv[m0 + r4]     = 1.f / lrA;
                linv[m0 + r4 + 8] = 1.f / lrB;
            }
        }
        __syncthreads();

        // ---- PV: O^T[d,q] += V^T P^T ; warp owns d-rows [m0, m0+16) ----
        #pragma unroll
        for (int j = 0; j < 8; j++) {
            float a0 = alphas[j*8 + 2*l4];
            float a1 = alphas[j*8 + 2*l4 + 1];
            oacc[j][0] *= a0; oacc[j][1] *= a1;
            oacc[j][2] *= a0; oacc[j][3] *= a1;
        }
        #pragma unroll
        for (int kh = 0; kh < 4; kh++) {
            uint32_t af[4];
            ldm_x4_t(af, vs_b + (uint32_t)((kh*16 + v_s)*ASS + m0 + v_d8)*2);
            #pragma unroll
            for (int jb = 0; jb < 4; jb++) {
                uint32_t bf[4];
                ldm_x4(bf, ps_b + (uint32_t)((jb*16 + b_row)*ASS + kh*16 + b_k8)*2);
                mma_f16(oacc[jb*2],     af, bf);
                mma_f16(oacc[jb*2 + 1], af, bf + 2);
            }
        }
    }

    // ---- output fp16: O[b, q, h*64 + d] ----
    #pragma unroll
    for (int j = 0; j < 8; j++) {
        int qc2 = j*8 + 2*l4;
        float i0 = linv[qc2], i1 = linv[qc2 + 1];
        int d0 = m0 + r4;
        size_t ro0 = ((size_t)b*SEQ + q0 + qc2)*DMODEL + h*DHEAD;
        size_t ro1 = ro0 + DMODEL;
        Op[ro0 + d0]     = __float2half_rn(oacc[j][0]*i0);
        Op[ro1 + d0]     = __float2half_rn(oacc[j][1]*i1);
        Op[ro0 + d0 + 8] = __float2half_rn(oacc[j][2]*i0);
        Op[ro1 + d0 + 8] = __float2half_rn(oacc[j][3]*i1);
    }
}

// ---------------------------------------------------------------------------
// Host-side stream/event resources (static-init, pre-checkpoint).
// ---------------------------------------------------------------------------
struct StreamCtx {
    cudaStream_t s1 = nullptr;
    cudaEvent_t root = nullptr, enc = nullptr, dec0 = nullptr, kv[NLAYER] = {};
    bool ok = false;
    StreamCtx() {
        if (cudaStreamCreateWithFlags(&s1, cudaStreamNonBlocking) != cudaSuccess) return;
        if (cudaEventCreateWithFlags(&root, cudaEventDisableTiming) != cudaSuccess) return;
        if (cudaEventCreateWithFlags(&enc,  cudaEventDisableTiming) != cudaSuccess) return;
        if (cudaEventCreateWithFlags(&dec0, cudaEventDisableTiming) != cudaSuccess) return;
        for (int i = 0; i < NLAYER; i++)
            if (cudaEventCreateWithFlags(&kv[i], cudaEventDisableTiming) != cudaSuccess) return;
        ok = true;
    }
};
static StreamCtx g_sc;

// ---------------------------------------------------------------------------
// Orchestration (R10 layout)
// ---------------------------------------------------------------------------
static inline void launch_gemm(const __half* A, const __half* W, const float* bias,
                               const float* res, void* C, int M, int N, int K,
                               bool relu, cudaStream_t st) {
    if (N <= 1024) {
        dim3 grid(N/128, M/64), block(256);
        if (res)        gemm_mma64<false,true ,true ,false><<<grid, block, GEMM64_SMEM, st>>>(A, W, bias, res, C, M, N, K);
        else if (relu)  gemm_mma64<true ,false,true ,true ><<<grid, block, GEMM64_SMEM, st>>>(A, W, bias, nullptr, C, M, N, K);
        else if (bias)  gemm_mma64<false,false,true ,true ><<<grid, block, GEMM64_SMEM, st>>>(A, W, bias, nullptr, C, M, N, K);
        else            gemm_mma64<false,false,false,false><<<grid, block, GEMM64_SMEM, st>>>(A, W, nullptr, nullptr, C, M, N, K);
        return;
    }
    dim3 grid(N/128, M/128), block(256);
    if (res)        gemm_mma<false,true ,true ,false><<<grid, block, GEMM_SMEM, st>>>(A, W, bias, res, C, M, N, K);
    else if (relu)  gemm_mma<true ,false,true ,true ><<<grid, block, GEMM_SMEM, st>>>(A, W, bias, nullptr, C, M, N, K);
    else if (bias)  gemm_mma<false,false,true ,true ><<<grid, block, GEMM_SMEM, st>>>(A, W, bias, nullptr, C, M, N, K);
    else            gemm_mma<false,false,false,false><<<grid, block, GEMM_SMEM, st>>>(A, W, nullptr, nullptr, C, M, N, K);
}

extern "C" void kernel_launch(void* const* d_in, const int* in_sizes, int n_in,
                              void* d_out, int out_size) {
    const int*   src        = (const int*)  d_in[0];
    const int*   tgt        = (const int*)  d_in[1];
    const float* emb        = (const float*)d_in[2];
    const float* enc_attn_w = (const float*)d_in[3];
    const float* enc_attn_b = (const float*)d_in[4];
    const float* enc_ln_g   = (const float*)d_in[5];
    const float* enc_ln_b   = (const float*)d_in[6];
    const float* enc_w1     = (const float*)d_in[7];
    const float* enc_b1     = (const float*)d_in[8];
    const float* enc_w2     = (const float*)d_in[9];
    const float* enc_b2     = (const float*)d_in[10];
    const float* dec_attn_w = (const float*)d_in[11];
    const float* dec_attn_b = (const float*)d_in[12];
    const float* dec_ln_g   = (const float*)d_in[13];
    const float* dec_ln_b   = (const float*)d_in[14];
    const float* dec_w1     = (const float*)d_in[15];
    const float* dec_b1     = (const float*)d_in[16];
    const float* dec_w2     = (const float*)d_in[17];
    const float* dec_b2     = (const float*)d_in[18];
    const float* enc_norm_g = (const float*)d_in[19];
    const float* enc_norm_b = (const float*)d_in[20];
    const float* dec_norm_g = (const float*)d_in[21];
    const float* dec_norm_b = (const float*)d_in[22];

    float *x, *xd;
    __half *x2, *x2d, *qb, *ctx, *ctxd, *enc, *hbuf, *qkv, *qkvd, *wv;
    __half *kvb[NLAYER];
    cudaGetSymbolAddress((void**)&x,    g_x);
    cudaGetSymbolAddress((void**)&xd,   g_xd);
    cudaGetSymbolAddress((void**)&x2,   g_x2);
    cudaGetSymbolAddress((void**)&x2d,  g_x2d);
    cudaGetSymbolAddress((void**)&qb,   g_qb);
    cudaGetSymbolAddress((void**)&ctx,  g_ctx);
    cudaGetSymbolAddress((void**)&ctxd, g_ctxd);
    cudaGetSymbolAddress((void**)&enc,  g_enc);
    cudaGetSymbolAddress((void**)&hbuf, g_h);
    cudaGetSymbolAddress((void**)&qkv,  g_qkv);
    cudaGetSymbolAddress((void**)&qkvd, g_qkvd);
    cudaGetSymbolAddress((void**)&wv,   g_w);
    {
        __half* kvb0;
        cudaGetSymbolAddress((void**)&kvb0, g_kvb);
        for (int l = 0; l < NLAYER; l++) kvb[l] = kvb0 + (size_t)l*MROWS*2*DMODEL;
    }

    cudaFuncSetAttribute(attn_mma, cudaFuncAttributeMaxDynamicSharedMemorySize, ATTN_SMEM);
    cudaFuncSetAttribute(gemm_mma<false,true ,true ,false>, cudaFuncAttributeMaxDynamicSharedMemorySize, GEMM_SMEM);
    cudaFuncSetAttribute(gemm_mma<true ,false,true ,true >, cudaFuncAttributeMaxDynamicSharedMemorySize, GEMM_SMEM);
    cudaFuncSetAttribute(gemm_mma<false,false,true ,true >, cudaFuncAttributeMaxDynamicSharedMemorySize, GEMM_SMEM);
    cudaFuncSetAttribute(gemm_mma<false,false,false,false>, cudaFuncAttributeMaxDynamicSharedMemorySize, GEMM_SMEM);
    cudaFuncSetAttribute(gemm_mma64<false,true ,true ,false>, cudaFuncAttributeMaxDynamicSharedMemorySize, GEMM64_SMEM);
    cudaFuncSetAttribute(gemm_mma64<true ,false,true ,true >, cudaFuncAttributeMaxDynamicSharedMemorySize, GEMM64_SMEM);
    cudaFuncSetAttribute(gemm_mma64<false,false,true ,true >, cudaFuncAttributeMaxDynamicSharedMemorySize, GEMM64_SMEM);
    cudaFuncSetAttribute(gemm_mma64<false,false,false,false>, cudaFuncAttributeMaxDynamicSharedMemorySize, GEMM64_SMEM);

    const int D = DMODEL, M = MROWS;
    const size_t WSZ = (size_t)D*D;
    dim3 attnGrid(SEQ/64, NHEAD, BATCH);
    const __half* ew = wv + OFF_ENC_ATTN;
    const __half* dw = wv + OFF_DEC_ATTN;

    const bool par = g_sc.ok;
    cudaStream_t s0 = 0;
    cudaStream_t s1 = par ? g_sc.s1 : (cudaStream_t)0;

    if (par) {
        cudaEventRecord(g_sc.root, s0);
        cudaStreamWaitEvent(s1, g_sc.root, 0);
    }

    // ----- s1: decoder-side cvt + embed + layer-0 self-attn block -----
    cvt_kernel<<<(NLAYER*8*DMODEL*DMODEL)/2048, 256, 0, s1>>>(dec_attn_w, wv + OFF_DEC_ATTN, NLAYER*8*DMODEL*DMODEL);
    cvt_kernel<<<(NLAYER*DFF*DMODEL)/2048,      256, 0, s1>>>(dec_w1,     wv + OFF_DEC_W1,   NLAYER*DFF*DMODEL);
    cvt_kernel<<<(NLAYER*DMODEL*DFF)/2048,      256, 0, s1>>>(dec_w2,     wv + OFF_DEC_W2,   NLAYER*DMODEL*DFF);
    cvt_kernel<<<(VOCAB*DMODEL)/2048,           256, 0, s1>>>(emb,        wv + OFF_EMB,      VOCAB*DMODEL);
    embed_kernel<<<M, 128, 0, s1>>>(tgt, emb, xd);
    {
        const __half* w  = dw;
        const float*  bb = dec_attn_b;
        ln_kernel<<<M/8, 256, 0, s1>>>(xd, dec_ln_g, dec_ln_b, x2d);
        launch_gemm(x2d, w, bb, nullptr, qkvd, M, 3*D, D, false, s1);
        attn_mma<<<attnGrid, 128, ATTN_SMEM, s1>>>(qkvd, 3*D, qkvd + D, qkvd + 2*D, 3*D, ctxd, tgt, 1);
        launch_gemm(ctxd, w + 3*WSZ, bb + 3*D, xd, xd, M, D, D, false, s1);
        ln_kernel<<<M/8, 256, 0, s1>>>(xd, dec_ln_g + (size_t)1*D, dec_ln_b + (size_t)1*D, x2d);
    }
    if (par) cudaEventRecord(g_sc.dec0, s1);

    // ----- s0: encoder-side cvt + embed + encoder -----
    cvt_kernel<<<(NLAYER*4*DMODEL*DMODEL)/2048, 256, 0, s0>>>(enc_attn_w, wv + OFF_ENC_ATTN, NLAYER*4*DMODEL*DMODEL);
    cvt_kernel<<<(NLAYER*DFF*DMODEL)/2048,      256, 0, s0>>>(enc_w1,     wv + OFF_ENC_W1,   NLAYER*DFF*DMODEL);
    cvt_kernel<<<(NLAYER*DMODEL*DFF)/2048,      256, 0, s0>>>(enc_w2,     wv + OFF_ENC_W2,   NLAYER*DMODEL*DFF);
    embed_kernel<<<M, 128, 0, s0>>>(src, emb, x);
    for (int l = 0; l < NLAYER; l++) {
        const __half* w  = ew + (size_t)l*4*WSZ;
        const float*  bb = enc_attn_b + (size_t)l*4*D;
        ln_kernel<<<M/8, 256, 0, s0>>>(x, enc_ln_g + (size_t)(l*2+0)*D, enc_ln_b + (size_t)(l*2+0)*D, x2);
        launch_gemm(x2, w, bb, nullptr, qkv, M, 3*D, D, false, s0);
        attn_mma<<<attnGrid, 128, ATTN_SMEM, s0>>>(qkv, 3*D, qkv + D, qkv + 2*D, 3*D, ctx, src, 0);
        launch_gemm(ctx, w + 3*WSZ, bb + 3*D, x, x, M, D, D, false, s0);
        ln_kernel<<<M/8, 256, 0, s0>>>(x, enc_ln_g + (size_t)(l*2+1)*D, enc_ln_b + (size_t)(l*2+1)*D, x2);
        launch_gemm(x2, wv + OFF_ENC_W1 + (size_t)l*DFF*D, enc_b1 + (size_t)l*DFF, nullptr, hbuf, M, DFF, D, true, s0);
        launch_gemm(hbuf, wv + OFF_ENC_W2 + (size_t)l*D*DFF, enc_b2 + (size_t)l*D, x, x, M, D, DFF, false, s0);
    }
    ln_kernel<<<M/8, 256, 0, s0>>>(x, enc_norm_g, enc_norm_b, enc);
    if (par) cudaEventRecord(g_sc.enc, s0);

    // ----- s1: cross-KV projections (need enc) -----
    if (par) cudaStreamWaitEvent(s1, g_sc.enc, 0);
    for (int l = 0; l < NLAYER; l++) {
        const __half* w  = dw + (size_t)l*8*WSZ;
        const float*  bb = dec_attn_b + (size_t)l*8*D;
        launch_gemm(enc, w + 5*WSZ, bb + 5*D, nullptr, kvb[l], M, 2*D, D, false, s1);
        if (par) cudaEventRecord(g_sc.kv[l], s1);
    }

    // ----- s0: decoder -----
    if (par) cudaStreamWaitEvent(s0, g_sc.dec0, 0);
    for (int l = 0; l < NLAYER; l++) {
        const __half* w  = dw + (size_t)l*8*WSZ;
        const float*  bb = dec_attn_b + (size_t)l*8*D;
        if (l > 0) {
            ln_kernel<<<M/8, 256, 0, s0>>>(xd, dec_ln_g + (size_t)(l*3+0)*D, dec_ln_b + (size_t)(l*3+0)*D, x2d);
            launch_gemm(x2d, w, bb, nullptr, qkvd, M, 3*D, D, false, s0);
            attn_mma<<<attnGrid, 128, ATTN_SMEM, s0>>>(qkvd, 3*D, qkvd + D, qkvd + 2*D, 3*D, ctxd, tgt, 1);
            launch_gemm(ctxd, w + 3*WSZ, bb + 3*D, xd, xd, M, D, D, false, s0);
            ln_kernel<<<M/8, 256, 0, s0>>>(xd, dec_ln_g + (size_t)(l*3+1)*D, dec_ln_b + (size_t)(l*3+1)*D, x2d);
        }
        launch_gemm(x2d, w + 4*WSZ, bb + 4*D, nullptr, qb, M, D, D, false, s0);
        if (par) cudaStreamWaitEvent(s0, g_sc.kv[l], 0);
        attn_mma<<<attnGrid, 128, ATTN_SMEM, s0>>>(qb, D, kvb[l], kvb[l] + D, 2*D, ctxd, src, 0);
        launch_gemm(ctxd, w + 7*WSZ, bb + 7*D, xd, xd, M, D, D, false, s0);
        ln_kernel<<<M/8, 256, 0, s0>>>(xd, dec_ln_g + (size_t)(l*3+2)*D, dec_ln_b + (size_t)(l*3+2)*D, x2d);
        launch_gemm(x2d, wv + OFF_DEC_W1 + (size_t)l*DFF*D, dec_b1 + (size_t)l*DFF, nullptr, hbuf, M, DFF, D, true, s0);
        launch_gemm(hbuf, wv + OFF_DEC_W2 + (size_t)l*D*DFF, dec_b2 + (size_t)l*D, xd, xd, M, D, DFF, false, s0);
    }
    ln_kernel<<<M/8, 256, 0, s0>>>(xd, dec_norm_g, dec_norm_b, x2d);

    // ----- tied output projection -----
    launch_gemm(x2d, wv + OFF_EMB, nullptr, nullptr, (float*)d_out, M, VOCAB, D, false, s0);
}

// round 15
// speedup vs baseline: 1.5439x; 1.5439x over previous
#include <cuda_runtime.h>
#include <cuda_fp16.h>
#include <cstdint>
#include <math.h>

// ---------------------------------------------------------------------------
// Problem constants
// ---------------------------------------------------------------------------
#define BATCH 8
#define SEQ   512
#define DMODEL 512
#define NHEAD 8
#define DHEAD 64
#define NLAYER 4
#define DFF   2048
#define VOCAB 32000
#define MROWS (BATCH*SEQ)   // 4096

__device__ __forceinline__ uint32_t smem_u32(const void* p) {
    uint32_t a;
    asm("{ .reg .u64 t; cvta.to.shared.u64 t, %1; cvt.u32.u64 %0, t; }" : "=r"(a) : "l"(p));
    return a;
}
__device__ __forceinline__ void cp16(uint32_t s, const void* g) {
    asm volatile("cp.async.cg.shared.global [%0], [%1], 16;" :: "r"(s), "l"(g));
}
#define CP_COMMIT() asm volatile("cp.async.commit_group;" ::: "memory")
template<int N> __device__ __forceinline__ void cp_wait() {
    asm volatile("cp.async.wait_group %0;" :: "n"(N) : "memory");
}
__device__ __forceinline__ void ldm_x4(uint32_t* r, uint32_t addr) {
    asm volatile("ldmatrix.sync.aligned.m8n8.x4.shared.b16 {%0,%1,%2,%3}, [%4];"
        : "=r"(r[0]), "=r"(r[1]), "=r"(r[2]), "=r"(r[3]) : "r"(addr));
}
__device__ __forceinline__ void ldm_x4_t(uint32_t* r, uint32_t addr) {
    asm volatile("ldmatrix.sync.aligned.m8n8.x4.trans.shared.b16 {%0,%1,%2,%3}, [%4];"
        : "=r"(r[0]), "=r"(r[1]), "=r"(r[2]), "=r"(r[3]) : "r"(addr));
}
__device__ __forceinline__ void mma_f16(float* c, const uint32_t* a, const uint32_t* b) {
    asm volatile(
        "mma.sync.aligned.m16n8k16.row.col.f32.f16.f16.f32 "
        "{%0,%1,%2,%3}, {%4,%5,%6,%7}, {%8,%9}, {%0,%1,%2,%3};"
        : "+f"(c[0]), "+f"(c[1]), "+f"(c[2]), "+f"(c[3])
        : "r"(a[0]), "r"(a[1]), "r"(a[2]), "r"(a[3]), "r"(b[0]), "r"(b[1]));
}

// ---------------------------------------------------------------------------
// Scratch (device globals; no allocation allowed)
// ---------------------------------------------------------------------------
__device__ __align__(16) float  g_x   [MROWS*DMODEL];
__device__ __align__(16) float  g_xd  [MROWS*DMODEL];
__device__ __align__(16) __half g_x2  [MROWS*DMODEL];
__device__ __align__(16) __half g_x2d [MROWS*DMODEL];
__device__ __align__(16) __half g_qb  [MROWS*DMODEL];
__device__ __align__(16) __half g_ctx [MROWS*DMODEL];
__device__ __align__(16) __half g_ctxd[MROWS*DMODEL];
__device__ __align__(16) __half g_enc [MROWS*DMODEL];
__device__ __align__(16) __half g_h   [MROWS*DFF];
__device__ __align__(16) __half g_qkv [MROWS*3*DMODEL];
__device__ __align__(16) __half g_qkvd[MROWS*3*DMODEL];
__device__ __align__(16) __half g_kvb [NLAYER][MROWS*2*DMODEL];

// converted-weight arena (fp16)
#define OFF_ENC_ATTN 0
#define OFF_ENC_W1   (OFF_ENC_ATTN + NLAYER*4*DMODEL*DMODEL)
#define OFF_ENC_W2   (OFF_ENC_W1   + NLAYER*DFF*DMODEL)
#define OFF_DEC_ATTN (OFF_ENC_W2   + NLAYER*DMODEL*DFF)
#define OFF_DEC_W1   (OFF_DEC_ATTN + NLAYER*8*DMODEL*DMODEL)
#define OFF_DEC_W2   (OFF_DEC_W1   + NLAYER*DFF*DMODEL)
#define OFF_EMB      (OFF_DEC_W2   + NLAYER*DMODEL*DFF)
#define W_TOTAL      (OFF_EMB      + VOCAB*DMODEL)
__device__ __align__(16) __half g_w[W_TOTAL];

// ---------------------------------------------------------------------------
// fp32 -> fp16 conversion
// ---------------------------------------------------------------------------
__global__ void cvt_kernel(const float* __restrict__ in, __half* __restrict__ out, int n) {
    int i = (blockIdx.x*blockDim.x + threadIdx.x)*8;
    if (i < n) {
        float4 a = *(const float4*)(in + i);
        float4 b = *(const float4*)(in + i + 4);
        __half2 h0 = __floats2half2_rn(a.x, a.y);
        __half2 h1 = __floats2half2_rn(a.z, a.w);
        __half2 h2 = __floats2half2_rn(b.x, b.y);
        __half2 h3 = __floats2half2_rn(b.z, b.w);
        uint4 o;
        o.x = *(uint32_t*)&h0; o.y = *(uint32_t*)&h1;
        o.z = *(uint32_t*)&h2; o.w = *(uint32_t*)&h3;
        *(uint4*)(out + i) = o;
    }
}

// ---------------------------------------------------------------------------
// Embedding + sinusoidal positional encoding (residual stream, fp32)
// ---------------------------------------------------------------------------
__global__ void embed_kernel(const int* __restrict__ tok,
                             const float* __restrict__ emb,
                             float* __restrict__ y) {
    int row = blockIdx.x;
    int s   = row % SEQ;
    int t   = tok[row];
    const float scale = 22.62741699796952f;
    const float c0 = -9.210340371976184f / (float)DMODEL;
    int tid = threadIdx.x;
    #pragma unroll
    for (int i = 0; i < 4; i++) {
        int d = tid + i*128;
        float e = (t == 0) ? 0.f : emb[(size_t)t*DMODEL + d];
        int half = d >> 1;
        float div = expf((float)(2*half) * c0);
        float ang = (float)s * div;
        float pe = (d & 1) ? cosf(ang) : sinf(ang);
        y[(size_t)row*DMODEL + d] = e*scale + pe;
    }
}

// ---------------------------------------------------------------------------
// LayerNorm, warp-per-row (8 rows / 256-thread block).
// ---------------------------------------------------------------------------
__global__ __launch_bounds__(256)
void ln_kernel(const float* __restrict__ x,
               const float* __restrict__ g,
               const float* __restrict__ b,
               __half* __restrict__ y) {
    int row  = blockIdx.x*8 + (threadIdx.x >> 5);
    int lane = threadIdx.x & 31;
    const float* xr = x + (size_t)row*DMODEL;
    float4 v[4];
    float s = 0.f;
    #pragma unroll
    for (int c = 0; c < 4; c++) {
        v[c] = *(const float4*)(xr + lane*4 + c*128);
        s += (v[c].x + v[c].y) + (v[c].z + v[c].w);
    }
    #pragma unroll
    for (int o = 16; o > 0; o >>= 1) s += __shfl_xor_sync(0xffffffffu, s, o);
    float mean = s * (1.f/(float)DMODEL);
    float vs = 0.f;
    #pragma unroll
    for (int c = 0; c < 4; c++) {
        float d0 = v[c].x-mean, d1 = v[c].y-mean, d2 = v[c].z-mean, d3 = v[c].w-mean;
        vs += d0*d0 + d1*d1 + d2*d2 + d3*d3;
    }
    #pragma unroll
    for (int o = 16; o > 0; o >>= 1) vs += __shfl_xor_sync(0xffffffffu, vs, o);
    float inv = rsqrtf(vs * (1.f/(float)DMODEL) + 1e-5f);
    #pragma unroll
    for (int c = 0; c < 4; c++) {
        int d = lane*4 + c*128;
        float4 gv = *(const float4*)(g + d);
        float4 bv = *(const float4*)(b + d);
        float r0 = (v[c].x-mean)*inv*gv.x + bv.x;
        float r1 = (v[c].y-mean)*inv*gv.y + bv.y;
        float r2 = (v[c].z-mean)*inv*gv.z + bv.z;
        float r3 = (v[c].w-mean)*inv*gv.w + bv.w;
        __half2 h0 = __floats2half2_rn(r0, r1);
        __half2 h1 = __floats2half2_rn(r2, r3);
        uint2 o; o.x = *(uint32_t*)&h0; o.y = *(uint32_t*)&h1;
        *(uint2*)(y + (size_t)row*DMODEL + d) = o;
    }
}

// ---------------------------------------------------------------------------
// fp16 mma.sync GEMM, CTA 128x128x32 (wide-N shapes).
// ---------------------------------------------------------------------------
#define TSTR 40
#define TILE_HALFS (128*TSTR)
#define STAGE_HALFS (2*TILE_HALFS)
#define GEMM_SMEM (3*STAGE_HALFS*2)

template<bool RELU, bool RES, bool BIAS, bool OHALF>
__global__ __launch_bounds__(256, 2)
void gemm_mma(const __half* __restrict__ A, const __half* __restrict__ W,
              const float* __restrict__ bias, const float* __restrict__ res,
              void* __restrict__ Cv, int M, int N, int K) {
    extern __shared__ __half smh[];
    int t = threadIdx.x, lane = t & 31, wid = t >> 5;
    int wm = (wid & 1) * 64;
    int wn = (wid >> 1) * 32;
    int r4 = lane >> 2, l4 = lane & 3;

    const __half* Ab = A + (size_t)blockIdx.y*128*K;
    const __half* Wb = W + (size_t)blockIdx.x*128*K;
    uint32_t sbase = smem_u32(smh);

    float acc[4][4][4];
    #pragma unroll
    for (int i = 0; i < 4; i++)
        #pragma unroll
        for (int j = 0; j < 4; j++)
            #pragma unroll
            for (int c = 0; c < 4; c++) acc[i][j][c] = 0.f;

    int NK = K >> 5;

    auto issue = [&](int it, int buf) {
        uint32_t base = sbase + (uint32_t)buf*STAGE_HALFS*2;
        int k0 = it*32;
        #pragma unroll
        for (int i = 0; i < 2; i++) {
            int idx = t + i*256, r = idx >> 2, ch = idx & 3;
            uint32_t off = (uint32_t)(r*TSTR + ch*8)*2;
            cp16(base + off,                  Ab + (size_t)r*K + k0 + ch*8);
            cp16(base + TILE_HALFS*2 + off,   Wb + (size_t)r*K + k0 + ch*8);
        }
        CP_COMMIT();
    };

    issue(0, 0);
    issue(1, 1);

    int a_row = (lane & 15);
    int a_kh8 = (lane >> 4) * 8;
    int b_row = (lane & 7) + ((lane >> 4) & 1) * 8;
    int b_kh8 = ((lane >> 3) & 1) * 8;

    for (int it = 0; it < NK; it++) {
        if (it + 1 < NK) cp_wait<1>(); else cp_wait<0>();
        __syncthreads();
        if (it + 2 < NK) issue(it + 2, (it + 2) % 3);
        uint32_t sA = sbase + (uint32_t)(it % 3)*STAGE_HALFS*2;
        uint32_t sB = sA + TILE_HALFS*2;
        #pragma unroll
        for (int kh = 0; kh < 2; kh++) {
            uint32_t af[4][4], bf[2][4];
            #pragma unroll
            for (int mi = 0; mi < 4; mi++)
                ldm_x4(af[mi], sA + (uint32_t)((wm + mi*16 + a_row)*TSTR + kh*16 + a_kh8)*2);
            #pragma unroll
            for (int nb = 0; nb < 2; nb++)
                ldm_x4(bf[nb], sB + (uint32_t)((wn + nb*16 + b_row)*TSTR + kh*16 + b_kh8)*2);
            #pragma unroll
            for (int mi = 0; mi < 4; mi++) {
                #pragma unroll
                for (int ni = 0; ni < 4; ni++)
                    mma_f16(acc[mi][ni], af[mi], bf[ni >> 1] + (ni & 1)*2);
            }
        }
    }

    int gm = blockIdx.y*128 + wm;
    int gn = blockIdx.x*128 + wn;
    #pragma unroll
    for (int mi = 0; mi < 4; mi++) {
        #pragma unroll
        for (int ni = 0; ni < 4; ni++) {
            int row = gm + mi*16 + r4;
            int col = gn + ni*8 + l4*2;
            float2 v0 = make_float2(acc[mi][ni][0], acc[mi][ni][1]);
            float2 v1 = make_float2(acc[mi][ni][2], acc[mi][ni][3]);
            if (BIAS) {
                float2 bv = *(const float2*)(bias + col);
                v0.x += bv.x; v0.y += bv.y; v1.x += bv.x; v1.y += bv.y;
            }
            if (RELU) {
                v0.x = fmaxf(v0.x, 0.f); v0.y = fmaxf(v0.y, 0.f);
                v1.x = fmaxf(v1.x, 0.f); v1.y = fmaxf(v1.y, 0.f);
            }
            if (RES) {
                float2 r0 = *(const float2*)(res + (size_t)row*N + col);
                float2 r1 = *(const float2*)(res + (size_t)(row+8)*N + col);
                v0.x += r0.x; v0.y += r0.y; v1.x += r1.x; v1.y += r1.y;
            }
            if (OHALF) {
                __half* C = (__half*)Cv;
                *(__half2*)(C + (size_t)row*N + col)     = __floats2half2_rn(v0.x, v0.y);
                *(__half2*)(C + (size_t)(row+8)*N + col) = __floats2half2_rn(v1.x, v1.y);
            } else {
                float* C = (float*)Cv;
                *(float2*)(C + (size_t)row*N + col)     = v0;
                *(float2*)(C + (size_t)(row+8)*N + col) = v1;
            }
        }
    }
}

// ---------------------------------------------------------------------------
// fp16 mma.sync GEMM, CTA 64x128x32 (narrow-N shapes).
// ---------------------------------------------------------------------------
#define A64_HALFS (64*TSTR)
#define S64_HALFS (A64_HALFS + TILE_HALFS)
#define GEMM64_SMEM (3*S64_HALFS*2)

template<bool RELU, bool RES, bool BIAS, bool OHALF>
__global__ __launch_bounds__(256)
void gemm_mma64(const __half* __restrict__ A, const __half* __restrict__ W,
                const float* __restrict__ bias, const float* __restrict__ res,
                void* __restrict__ Cv, int M, int N, int K) {
    extern __shared__ __half smh[];
    int t = threadIdx.x, lane = t & 31, wid = t >> 5;
    int wm = (wid & 1) * 32;
    int wn = (wid >> 1) * 32;
    int r4 = lane >> 2, l4 = lane & 3;

    const __half* Ab = A + (size_t)blockIdx.y*64*K;
    const __half* Wb = W + (size_t)blockIdx.x*128*K;
    uint32_t sbase = smem_u32(smh);

    float acc[2][4][4];
    #pragma unroll
    for (int i = 0; i < 2; i++)
        #pragma unroll
        for (int j = 0; j < 4; j++)
            #pragma unroll
            for (int c = 0; c < 4; c++) acc[i][j][c] = 0.f;

    int NK = K >> 5;

    auto issue = [&](int it, int buf) {
        uint32_t base = sbase + (uint32_t)buf*S64_HALFS*2;
        int k0 = it*32;
        {
            int r = t >> 2, ch = t & 3;
            cp16(base + (uint32_t)(r*TSTR + ch*8)*2, Ab + (size_t)r*K + k0 + ch*8);
        }
        #pragma unroll
        for (int i = 0; i < 2; i++) {
            int idx = t + i*256, r = idx >> 2, ch = idx & 3;
            cp16(base + A64_HALFS*2 + (uint32_t)(r*TSTR + ch*8)*2,
                 Wb + (size_t)r*K + k0 + ch*8);
        }
        CP_COMMIT();
    };

    issue(0, 0);
    issue(1, 1);

    int a_row = (lane & 15);
    int a_kh8 = (lane >> 4) * 8;
    int b_row = (lane & 7) + ((lane >> 4) & 1) * 8;
    int b_kh8 = ((lane >> 3) & 1) * 8;

    for (int it = 0; it < NK; it++) {
        if (it + 1 < NK) cp_wait<1>(); else cp_wait<0>();
        __syncthreads();
        if (it + 2 < NK) issue(it + 2, (it + 2) % 3);
        uint32_t sA = sbase + (uint32_t)(it % 3)*S64_HALFS*2;
        uint32_t sB = sA + A64_HALFS*2;
        #pragma unroll
        for (int kh = 0; kh < 2; kh++) {
            uint32_t af[2][4], bf[2][4];
            #pragma unroll
            for (int mi = 0; mi < 2; mi++)
                ldm_x4(af[mi], sA + (uint32_t)((wm + mi*16 + a_row)*TSTR + kh*16 + a_kh8)*2);
            #pragma unroll
            for (int nb = 0; nb < 2; nb++)
                ldm_x4(bf[nb], sB + (uint32_t)((wn + nb*16 + b_row)*TSTR + kh*16 + b_kh8)*2);
            #pragma unroll
            for (int mi = 0; mi < 2; mi++) {
                #pragma unroll
                for (int ni = 0; ni < 4; ni++)
                    mma_f16(acc[mi][ni], af[mi], bf[ni >> 1] + (ni & 1)*2);
            }
        }
    }

    int gm = blockIdx.y*64 + wm;
    int gn = blockIdx.x*128 + wn;
    #pragma unroll
    for (int mi = 0; mi < 2; mi++) {
        #pragma unroll
        for (int ni = 0; ni < 4; ni++) {
            int row = gm + mi*16 + r4;
            int col = gn + ni*8 + l4*2;
            float2 v0 = make_float2(acc[mi][ni][0], acc[mi][ni][1]);
            float2 v1 = make_float2(acc[mi][ni][2], acc[mi][ni][3]);
            if (BIAS) {
                float2 bv = *(const float2*)(bias + col);
                v0.x += bv.x; v0.y += bv.y; v1.x += bv.x; v1.y += bv.y;
            }
            if (RELU) {
                v0.x = fmaxf(v0.x, 0.f); v0.y = fmaxf(v0.y, 0.f);
                v1.x = fmaxf(v1.x, 0.f); v1.y = fmaxf(v1.y, 0.f);
            }
            if (RES) {
                float2 r0 = *(const float2*)(res + (size_t)row*N + col);
                float2 r1 = *(const float2*)(res + (size_t)(row+8)*N + col);
                v0.x += r0.x; v0.y += r0.y; v1.x += r1.x; v1.y += r1.y;
            }
            if (OHALF) {
                __half* C = (__half*)Cv;
                *(__half2*)(C + (size_t)row*N + col)     = __floats2half2_rn(v0.x, v0.y);
                *(__half2*)(C + (size_t)(row+8)*N + col) = __floats2half2_rn(v1.x, v1.y);
            } else {
                float* C = (float*)Cv;
                *(float2*)(C + (size_t)row*N + col)     = v0;
                *(float2*)(C + (size_t)(row+8)*N + col) = v1;
            }
        }
    }
}

// ---------------------------------------------------------------------------
// Flash attention, fp16 inputs, cp.async double-buffered K/V. (R10 exact)
// ---------------------------------------------------------------------------
#define ASS 72
#define ATILE (64*ASS)
#define FH_TOT (6*ATILE)
#define ATTN_SMEM (FH_TOT*2 + 2816)

__global__ __launch_bounds__(128)
void attn_mma(const __half* __restrict__ Qp, int qstride,
              const __half* __restrict__ Kp, const __half* __restrict__ Vp, int kvstride,
              __half* __restrict__ Op,
              const int* __restrict__ mtok, int causal) {
    extern __shared__ __half smh[];
    __half* Ps = smh + 5*ATILE;
    float* alphas = (float*)(smh + FH_TOT);
    float* linv   = alphas + 64;
    uint32_t* maskv = (uint32_t*)(linv + 64);

    int t = threadIdx.x, lane = t & 31, w = t >> 5;
    int r4 = lane >> 2, l4 = lane & 3;
    int q0 = blockIdx.x * 64, h = blockIdx.y, b = blockIdx.z;
    const __half* Qb = Qp + (size_t)b*SEQ*qstride  + h*DHEAD;
    const __half* Kb = Kp + (size_t)b*SEQ*kvstride + h*DHEAD;
    const __half* Vb = Vp + (size_t)b*SEQ*kvstride + h*DHEAD;

    uint32_t qs_b = smem_u32(smh);
    uint32_t ps_b = smem_u32(Ps);

    int a_row = (lane & 15);
    int a_k8  = (lane >> 4) * 8;
    int b_row = (lane & 7) + ((lane >> 4) & 1) * 8;
    int b_k8  = ((lane >> 3) & 1) * 8;
    int v_s   = (lane & 7) + ((lane >> 4) & 1) * 8;
    int v_d8  = ((lane >> 3) & 1) * 8;

    int qcnk = q0 >> 6;
    int nchunks = causal ? (qcnk + 1) : (SEQ/64);

    auto issue_kv = [&](int kt, int buf) {
        uint32_t kbase = qs_b + (uint32_t)(1 + buf)*ATILE*2;
        uint32_t vbase = qs_b + (uint32_t)(3 + buf)*ATILE*2;
        const __half* Kc = Kb + (size_t)kt*64*kvstride;
        const __half* Vc = Vb + (size_t)kt*64*kvstride;
        #pragma unroll
        for (int i = 0; i < 4; i++) {
            int idx = t + i*128, s = idx >> 3, ch = idx & 7;
            uint32_t off = (uint32_t)(s*ASS + ch*8)*2;
            cp16(kbase + off, Kc + (size_t)s*kvstride + ch*8);
            cp16(vbase + off, Vc + (size_t)s*kvstride + ch*8);
        }
        CP_COMMIT();
    };

    #pragma unroll
    for (int i = 0; i < 4; i++) {
        int idx = t + i*128, s = idx >> 3, ch = idx & 7;
        cp16(qs_b + (uint32_t)(s*ASS + ch*8)*2, Qb + (size_t)(q0+s)*qstride + ch*8);
    }
    CP_COMMIT();
    #pragma unroll
    for (int i = 0; i < 4; i++) {
        int idx = t + i*128;
        maskv[idx] = (mtok[b*SEQ + idx] != 0);
    }
    issue_kv(0, 0);
    cp_wait<1>();
    __syncthreads();

    int m0 = w*16;
    uint32_t qf[4][4];
    #pragma unroll
    for (int kh = 0; kh < 4; kh++)
        ldm_x4(qf[kh], qs_b + (uint32_t)((m0 + a_row)*ASS + kh*16 + a_k8)*2);

    float oacc[8][4];
    #pragma unroll
    for (int j = 0; j < 8; j++)
        #pragma unroll
        for (int c = 0; c < 4; c++) oacc[j][c] = 0.f;
    float mrA = -1e30f, mrB = -1e30f, lrA = 0.f, lrB = 0.f;
    int qA = q0 + m0 + r4, qB = qA + 8;

    for (int kt = 0; kt < nchunks; kt++) {
        cp_wait<0>();
        __syncthreads();
        if (kt + 1 < nchunks) issue_kv(kt + 1, (kt + 1) & 1);
        uint32_t ks_b = qs_b + (uint32_t)(1 + (kt & 1))*ATILE*2;
        uint32_t vs_b = qs_b + (uint32_t)(3 + (kt & 1))*ATILE*2;

        float sacc[8][4];
        #pragma unroll
        for (int j = 0; j < 8; j++)
            #pragma unroll
            for (int c = 0; c < 4; c++) sacc[j][c] = 0.f;
        #pragma unroll
        for (int kh = 0; kh < 4; kh++) {
            uint32_t bf[4][4];
            #pragma unroll
            for (int nb = 0; nb < 4; nb++)
                ldm_x4(bf[nb], ks_b + (uint32_t)((nb*16 + b_row)*ASS + kh*16 + b_k8)*2);
            #pragma unroll
            for (int nb = 0; nb < 4; nb++) {
                mma_f16(sacc[nb*2],     qf[kh], bf[nb]);
                mma_f16(sacc[nb*2 + 1], qf[kh], bf[nb] + 2);
            }
        }
        bool diag = causal && (kt == qcnk);
        float mA = -1e30f, mB = -1e30f;
        #pragma unroll
        for (int j = 0; j < 8; j++) {
            int kl = j*8 + 2*l4;
            int kg = kt*64 + kl;
            bool pv0 = maskv[kg] != 0, pv1 = maskv[kg+1] != 0;
            bool a0 = pv0 && (!diag || kg   <= qA);
            bool a1 = pv1 && (!diag || kg+1 <= qA);
            bool b0 = pv0 && (!diag || kg   <= qB);
            bool b1 = pv1 && (!diag || kg+1 <= qB);
            sacc[j][0] = a0 ? sacc[j][0]*0.125f : -1e9f;
            sacc[j][1] = a1 ? sacc[j][1]*0.125f : -1e9f;
            sacc[j][2] = b0 ? sacc[j][2]*0.125f : -1e9f;
            sacc[j][3] = b1 ? sacc[j][3]*0.125f : -1e9f;
            mA = fmaxf(mA, fmaxf(sacc[j][0], sacc[j][1]));
            mB = fmaxf(mB, fmaxf(sacc[j][2], sacc[j][3]));
        }
        mA = fmaxf(mA, __shfl_xor_sync(0xffffffffu, mA, 1));
        mA = fmaxf(mA, __shfl_xor_sync(0xffffffffu, mA, 2));
        mB = fmaxf(mB, __shfl_xor_sync(0xffffffffu, mB, 1));
        mB = fmaxf(mB, __shfl_xor_sync(0xffffffffu, mB, 2));
        float mnA = fmaxf(mrA, mA), mnB = fmaxf(mrB, mB);
        float aA = __expf(mrA - mnA), aB = __expf(mrB - mnB);
        mrA = mnA; mrB = mnB;
        float lA = 0.f, lB = 0.f;
        #pragma unroll
        for (int j = 0; j < 8; j++) {
            float p0 = __expf(sacc[j][0] - mnA);
            float p1 = __expf(sacc[j][1] - mnA);
            float p2 = __expf(sacc[j][2] - mnB);
            float p3 = __expf(sacc[j][3] - mnB);
            lA += p0 + p1; lB += p2 + p3;
            *(__half2*)(Ps + (m0 + r4)*ASS     + j*8 + 2*l4) = __floats2half2_rn(p0, p1);
            *(__half2*)(Ps + (m0 + r4 + 8)*ASS + j*8 + 2*l4) = __floats2half2_rn(p2, p3);
        }
        lA += __shfl_xor_sync(0xffffffffu, lA, 1);
        lA += __shfl_xor_sync(0xffffffffu, lA, 2);
        lB += __shfl_xor_sync(0xffffffffu, lB, 1);
        lB += __shfl_xor_sync(0xffffffffu, lB, 2);
        lrA = lrA*aA + lA;
        lrB = lrB*aB + lB;
        if (l4 == 0) {
            alphas[m0 + r4]     = aA;
            alphas[m0 + r4 + 8] = aB;
            if (kt == nchunks - 1) {
                linv[m0 + r4]     = 1.f / lrA;
                linv[m0 + r4 + 8] = 1.f / lrB;
            }
        }
        __syncthreads();

        #pragma unroll
        for (int j = 0; j < 8; j++) {
            float a0 = alphas[j*8 + 2*l4];
            float a1 = alphas[j*8 + 2*l4 + 1];
            oacc[j][0] *= a0; oacc[j][1] *= a1;
            oacc[j][2] *= a0; oacc[j][3] *= a1;
        }
        #pragma unroll
        for (int kh = 0; kh < 4; kh++) {
            uint32_t af[4];
            ldm_x4_t(af, vs_b + (uint32_t)((kh*16 + v_s)*ASS + m0 + v_d8)*2);
            #pragma unroll
            for (int jb = 0; jb < 4; jb++) {
                uint32_t bf[4];
                ldm_x4(bf, ps_b + (uint32_t)((jb*16 + b_row)*ASS + kh*16 + b_k8)*2);
                mma_f16(oacc[jb*2],     af, bf);
                mma_f16(oacc[jb*2 + 1], af, bf + 2);
            }
        }
    }

    #pragma unroll
    for (int j = 0; j < 8; j++) {
        int qc2 = j*8 + 2*l4;
        float i0 = linv[qc2], i1 = linv[qc2 + 1];
        int d0 = m0 + r4;
        size_t ro0 = ((size_t)b*SEQ + q0 + qc2)*DMODEL + h*DHEAD;
        size_t ro1 = ro0 + DMODEL;
        Op[ro0 + d0]     = __float2half_rn(oacc[j][0]*i0);
        Op[ro1 + d0]     = __float2half_rn(oacc[j][1]*i1);
        Op[ro0 + d0 + 8] = __float2half_rn(oacc[j][2]*i0);
        Op[ro1 + d0 + 8] = __float2half_rn(oacc[j][3]*i1);
    }
}

// ---------------------------------------------------------------------------
// Host-side stream/event resources (static-init, pre-checkpoint).
// ---------------------------------------------------------------------------
struct StreamCtx {
    cudaStream_t s1 = nullptr;
    cudaEvent_t root = nullptr, enc = nullptr, dec0 = nullptr, kv[NLAYER] = {};
    bool ok = false;
    StreamCtx() {
        if (cudaStreamCreateWithFlags(&s1, cudaStreamNonBlocking) != cudaSuccess) return;
        if (cudaEventCreateWithFlags(&root, cudaEventDisableTiming) != cudaSuccess) return;
        if (cudaEventCreateWithFlags(&enc,  cudaEventDisableTiming) != cudaSuccess) return;
        if (cudaEventCreateWithFlags(&dec0, cudaEventDisableTiming) != cudaSuccess) return;
        for (int i = 0; i < NLAYER; i++)
            if (cudaEventCreateWithFlags(&kv[i], cudaEventDisableTiming) != cudaSuccess) return;
        ok = true;
    }
};
static StreamCtx g_sc;

// ---------------------------------------------------------------------------
// Orchestration
// ---------------------------------------------------------------------------
static inline void launch_gemm(const __half* A, const __half* W, const float* bias,
                               const float* res, void* C, int M, int N, int K,
                               bool relu, cudaStream_t st) {
    if (N <= 1024) {
        dim3 grid(N/128, M/64), block(256);
        if (res)        gemm_mma64<false,true ,true ,false><<<grid, block, GEMM64_SMEM, st>>>(A, W, bias, res, C, M, N, K);
        else if (relu)  gemm_mma64<true ,false,true ,true ><<<grid, block, GEMM64_SMEM, st>>>(A, W, bias, nullptr, C, M, N, K);
        else if (bias)  gemm_mma64<false,false,true ,true ><<<grid, block, GEMM64_SMEM, st>>>(A, W, bias, nullptr, C, M, N, K);
        else            gemm_mma64<false,false,false,false><<<grid, block, GEMM64_SMEM, st>>>(A, W, nullptr, nullptr, C, M, N, K);
        return;
    }
    dim3 grid(N/128, M/128), block(256);
    if (res)        gemm_mma<false,true ,true ,false><<<grid, block, GEMM_SMEM, st>>>(A, W, bias, res, C, M, N, K);
    else if (relu)  gemm_mma<true ,false,true ,true ><<<grid, block, GEMM_SMEM, st>>>(A, W, bias, nullptr, C, M, N, K);
    else if (bias)  gemm_mma<false,false,true ,true ><<<grid, block, GEMM_SMEM, st>>>(A, W, bias, nullptr, C, M, N, K);
    else            gemm_mma<false,false,false,false><<<grid, block, GEMM_SMEM, st>>>(A, W, nullptr, nullptr, C, M, N, K);
}

extern "C" void kernel_launch(void* const* d_in, const int* in_sizes, int n_in,
                              void* d_out, int out_size) {
    const int*   src        = (const int*)  d_in[0];
    const int*   tgt        = (const int*)  d_in[1];
    const float* emb        = (const float*)d_in[2];
    const float* enc_attn_w = (const float*)d_in[3];
    const float* enc_attn_b = (const float*)d_in[4];
    const float* enc_ln_g   = (const float*)d_in[5];
    const float* enc_ln_b   = (const float*)d_in[6];
    const float* enc_w1     = (const float*)d_in[7];
    const float* enc_b1     = (const float*)d_in[8];
    const float* enc_w2     = (const float*)d_in[9];
    const float* enc_b2     = (const float*)d_in[10];
    const float* dec_attn_w = (const float*)d_in[11];
    const float* dec_attn_b = (const float*)d_in[12];
    const float* dec_ln_g   = (const float*)d_in[13];
    const float* dec_ln_b   = (const float*)d_in[14];
    const float* dec_w1     = (const float*)d_in[15];
    const float* dec_b1     = (const float*)d_in[16];
    const float* dec_w2     = (const float*)d_in[17];
    const float* dec_b2     = (const float*)d_in[18];
    const float* enc_norm_g = (const float*)d_in[19];
    const float* enc_norm_b = (const float*)d_in[20];
    const float* dec_norm_g = (const float*)d_in[21];
    const float* dec_norm_b = (const float*)d_in[22];

    float *x, *xd;
    __half *x2, *x2d, *qb, *ctx, *ctxd, *enc, *hbuf, *qkv, *qkvd, *wv;
    __half *kvb[NLAYER];
    cudaGetSymbolAddress((void**)&x,    g_x);
    cudaGetSymbolAddress((void**)&xd,   g_xd);
    cudaGetSymbolAddress((void**)&x2,   g_x2);
    cudaGetSymbolAddress((void**)&x2d,  g_x2d);
    cudaGetSymbolAddress((void**)&qb,   g_qb);
    cudaGetSymbolAddress((void**)&ctx,  g_ctx);
    cudaGetSymbolAddress((void**)&ctxd, g_ctxd);
    cudaGetSymbolAddress((void**)&enc,  g_enc);
    cudaGetSymbolAddress((void**)&hbuf, g_h);
    cudaGetSymbolAddress((void**)&qkv,  g_qkv);
    cudaGetSymbolAddress((void**)&qkvd, g_qkvd);
    cudaGetSymbolAddress((void**)&wv,   g_w);
    {
        __half* kvb0;
        cudaGetSymbolAddress((void**)&kvb0, g_kvb);
        for (int l = 0; l < NLAYER; l++) kvb[l] = kvb0 + (size_t)l*MROWS*2*DMODEL;
    }

    cudaFuncSetAttribute(attn_mma, cudaFuncAttributeMaxDynamicSharedMemorySize, ATTN_SMEM);
    cudaFuncSetAttribute(gemm_mma<false,true ,true ,false>, cudaFuncAttributeMaxDynamicSharedMemorySize, GEMM_SMEM);
    cudaFuncSetAttribute(gemm_mma<true ,false,true ,true >, cudaFuncAttributeMaxDynamicSharedMemorySize, GEMM_SMEM);
    cudaFuncSetAttribute(gemm_mma<false,false,true ,true >, cudaFuncAttributeMaxDynamicSharedMemorySize, GEMM_SMEM);
    cudaFuncSetAttribute(gemm_mma<false,false,false,false>, cudaFuncAttributeMaxDynamicSharedMemorySize, GEMM_SMEM);
    cudaFuncSetAttribute(gemm_mma64<false,true ,true ,false>, cudaFuncAttributeMaxDynamicSharedMemorySize, GEMM64_SMEM);
    cudaFuncSetAttribute(gemm_mma64<true ,false,true ,true >, cudaFuncAttributeMaxDynamicSharedMemorySize, GEMM64_SMEM);
    cudaFuncSetAttribute(gemm_mma64<false,false,true ,true >, cudaFuncAttributeMaxDynamicSharedMemorySize, GEMM64_SMEM);
    cudaFuncSetAttribute(gemm_mma64<false,false,false,false>, cudaFuncAttributeMaxDynamicSharedMemorySize, GEMM64_SMEM);

    const int D = DMODEL, M = MROWS;
    const size_t WSZ = (size_t)D*D;
    dim3 attnGrid(SEQ/64, NHEAD, BATCH);
    const __half* ew = wv + OFF_ENC_ATTN;
    const __half* dw = wv + OFF_DEC_ATTN;

    const bool par = g_sc.ok;
    cudaStream_t s0 = 0;
    cudaStream_t s1 = par ? g_sc.s1 : (cudaStream_t)0;

    if (par) {
        cudaEventRecord(g_sc.root, s0);
        cudaStreamWaitEvent(s1, g_sc.root, 0);
    }

    // ----- s1: decoder-side cvt + embed + layer-0 self-attn block -----
    cvt_kernel<<<(NLAYER*8*DMODEL*DMODEL)/2048, 256, 0, s1>>>(dec_attn_w, wv + OFF_DEC_ATTN, NLAYER*8*DMODEL*DMODEL);
    cvt_kernel<<<(NLAYER*DFF*DMODEL)/2048,      256, 0, s1>>>(dec_w1,     wv + OFF_DEC_W1,   NLAYER*DFF*DMODEL);
    cvt_kernel<<<(NLAYER*DMODEL*DFF)/2048,      256, 0, s1>>>(dec_w2,     wv + OFF_DEC_W2,   NLAYER*DMODEL*DFF);
    cvt_kernel<<<(VOCAB*DMODEL)/2048,           256, 0, s1>>>(emb,        wv + OFF_EMB,      VOCAB*DMODEL);
    embed_kernel<<<M, 128, 0, s1>>>(tgt, emb, xd);
    {
        const __half* w  = dw;
        const float*  bb = dec_attn_b;
        ln_kernel<<<M/8, 256, 0, s1>>>(xd, dec_ln_g, dec_ln_b, x2d);
        launch_gemm(x2d, w, bb, nullptr, qkvd, M, 3*D, D, false, s1);
        attn_mma<<<attnGrid, 128, ATTN_SMEM, s1>>>(qkvd, 3*D, qkvd + D, qkvd + 2*D, 3*D, ctxd, tgt, 1);
        launch_gemm(ctxd, w + 3*WSZ, bb + 3*D, xd, xd, M, D, D, false, s1);
        ln_kernel<<<M/8, 256, 0, s1>>>(xd, dec_ln_g + (size_t)1*D, dec_ln_b + (size_t)1*D, x2d);
    }
    if (par) cudaEventRecord(g_sc.dec0, s1);

    // ----- s0: encoder-side cvt + embed + encoder -----
    cvt_kernel<<<(NLAYER*4*DMODEL*DMODEL)/2048, 256, 0, s0>>>(enc_attn_w, wv + OFF_ENC_ATTN, NLAYER*4*DMODEL*DMODEL);
    cvt_kernel<<<(NLAYER*DFF*DMODEL)/2048,      256, 0, s0>>>(enc_w1,     wv + OFF_ENC_W1,   NLAYER*DFF*DMODEL);
    cvt_kernel<<<(NLAYER*DMODEL*DFF)/2048,      256, 0, s0>>>(enc_w2,     wv + OFF_ENC_W2,   NLAYER*DMODEL*DFF);
    embed_kernel<<<M, 128, 0, s0>>>(src, emb, x);
    for (int l = 0; l < NLAYER; l++) {
        const __half* w  = ew + (size_t)l*4*WSZ;
        const float*  bb = enc_attn_b + (size_t)l*4*D;
        ln_kernel<<<M/8, 256, 0, s0>>>(x, enc_ln_g + (size_t)(l*2+0)*D, enc_ln_b + (size_t)(l*2+0)*D, x2);
        launch_gemm(x2, w, bb, nullptr, qkv, M, 3*D, D, false, s0);
        attn_mma<<<attnGrid, 128, ATTN_SMEM, s0>>>(qkv, 3*D, qkv + D, qkv + 2*D, 3*D, ctx, src, 0);
        launch_gemm(ctx, w + 3*WSZ, bb + 3*D, x, x, M, D, D, false, s0);
        ln_kernel<<<M/8, 256, 0, s0>>>(x, enc_ln_g + (size_t)(l*2+1)*D, enc_ln_b + (size_t)(l*2+1)*D, x2);
        launch_gemm(x2, wv + OFF_ENC_W1 + (size_t)l*DFF*D, enc_b1 + (size_t)l*DFF, nullptr, hbuf, M, DFF, D, true, s0);
        launch_gemm(hbuf, wv + OFF_ENC_W2 + (size_t)l*D*DFF, enc_b2 + (size_t)l*D, x, x, M, D, DFF, false, s0);
    }
    ln_kernel<<<M/8, 256, 0, s0>>>(x, enc_norm_g, enc_norm_b, enc);
    if (par) cudaEventRecord(g_sc.enc, s0);

    // ----- s1: cross-KV projections (need enc) -----
    if (par) cudaStreamWaitEvent(s1, g_sc.enc, 0);
    for (int l = 0; l < NLAYER; l++) {
        const __half* w  = dw + (size_t)l*8*WSZ;
        const float*  bb = dec_attn_b + (size_t)l*8*D;
        launch_gemm(enc, w + 5*WSZ, bb + 5*D, nullptr, kvb[l], M, 2*D, D, false, s1);
        if (par) cudaEventRecord(g_sc.kv[l], s1);
    }

    // ----- s0: decoder -----
    if (par) cudaStreamWaitEvent(s0, g_sc.dec0, 0);
    for (int l = 0; l < NLAYER; l++) {
        const __half* w  = dw + (size_t)l*8*WSZ;
        const float*  bb = dec_attn_b + (size_t)l*8*D;
        if (l > 0) {
            ln_kernel<<<M/8, 256, 0, s0>>>(xd, dec_ln_g + (size_t)(l*3+0)*D, dec_ln_b + (size_t)(l*3+0)*D, x2d);
            launch_gemm(x2d, w, bb, nullptr, qkvd, M, 3*D, D, false, s0);
            attn_mma<<<attnGrid, 128, ATTN_SMEM, s0>>>(qkvd, 3*D, qkvd + D, qkvd + 2*D, 3*D, ctxd, tgt, 1);
            launch_gemm(ctxd, w + 3*WSZ, bb + 3*D, xd, xd, M, D, D, false, s0);
            ln_kernel<<<M/8, 256, 0, s0>>>(xd, dec_ln_g + (size_t)(l*3+1)*D, dec_ln_b + (size_t)(l*3+1)*D, x2d);
        }
        launch_gemm(x2d, w + 4*WSZ, bb + 4*D, nullptr, qb, M, D, D, false, s0);
        if (par) cudaStreamWaitEvent(s0, g_sc.kv[l], 0);
        attn_mma<<<attnGrid, 128, ATTN_SMEM, s0>>>(qb, D, kvb[l], kvb[l] + D, 2*D, ctxd, src, 0);
        launch_gemm(ctxd, w + 7*WSZ, bb + 7*D, xd, xd, M, D, D, false, s0);
        ln_kernel<<<M/8, 256, 0, s0>>>(xd, dec_ln_g + (size_t)(l*3+2)*D, dec_ln_b + (size_t)(l*3+2)*D, x2d);
        launch_gemm(x2d, wv + OFF_DEC_W1 + (size_t)l*DFF*D, dec_b1 + (size_t)l*DFF, nullptr, hbuf, M, DFF, D, true, s0);
        launch_gemm(hbuf, wv + OFF_DEC_W2 + (size_t)l*D*DFF, dec_b2 + (size_t)l*D, xd, xd, M, D, DFF, false, s0);
    }
    ln_kernel<<<M/8, 256, 0, s0>>>(xd, dec_norm_g, dec_norm_b, x2d);

    // ----- tied output projection -----
    launch_gemm(x2d, wv + OFF_EMB, nullptr, nullptr, (float*)d_out, M, VOCAB, D, false, s0);
}

// round 17
// speedup vs baseline: 1.6336x; 1.0581x over previous
#include <cuda_runtime.h>
#include <cuda_fp16.h>
#include <cstdint>
#include <math.h>

// ---------------------------------------------------------------------------
// Problem constants
// ---------------------------------------------------------------------------
#define BATCH 8
#define SEQ   512
#define DMODEL 512
#define NHEAD 8
#define DHEAD 64
#define NLAYER 4
#define DFF   2048
#define VOCAB 32000
#define MROWS (BATCH*SEQ)   // 4096

__device__ __forceinline__ uint32_t smem_u32(const void* p) {
    uint32_t a;
    asm("{ .reg .u64 t; cvta.to.shared.u64 t, %1; cvt.u32.u64 %0, t; }" : "=r"(a) : "l"(p));
    return a;
}
__device__ __forceinline__ void cp16(uint32_t s, const void* g) {
    asm volatile("cp.async.cg.shared.global [%0], [%1], 16;" :: "r"(s), "l"(g));
}
#define CP_COMMIT() asm volatile("cp.async.commit_group;" ::: "memory")
template<int N> __device__ __forceinline__ void cp_wait() {
    asm volatile("cp.async.wait_group %0;" :: "n"(N) : "memory");
}
__device__ __forceinline__ void ldm_x4(uint32_t* r, uint32_t addr) {
    asm volatile("ldmatrix.sync.aligned.m8n8.x4.shared.b16 {%0,%1,%2,%3}, [%4];"
        : "=r"(r[0]), "=r"(r[1]), "=r"(r[2]), "=r"(r[3]) : "r"(addr));
}
__device__ __forceinline__ void ldm_x4_t(uint32_t* r, uint32_t addr) {
    asm volatile("ldmatrix.sync.aligned.m8n8.x4.trans.shared.b16 {%0,%1,%2,%3}, [%4];"
        : "=r"(r[0]), "=r"(r[1]), "=r"(r[2]), "=r"(r[3]) : "r"(addr));
}
__device__ __forceinline__ void mma_f16(float* c, const uint32_t* a, const uint32_t* b) {
    asm volatile(
        "mma.sync.aligned.m16n8k16.row.col.f32.f16.f16.f32 "
        "{%0,%1,%2,%3}, {%4,%5,%6,%7}, {%8,%9}, {%0,%1,%2,%3};"
        : "+f"(c[0]), "+f"(c[1]), "+f"(c[2]), "+f"(c[3])
        : "r"(a[0]), "r"(a[1]), "r"(a[2]), "r"(a[3]), "r"(b[0]), "r"(b[1]));
}

// ---------------------------------------------------------------------------
// Scratch (device globals; no allocation allowed)
// ---------------------------------------------------------------------------
__device__ __align__(16) float  g_x   [MROWS*DMODEL];
__device__ __align__(16) float  g_xd  [MROWS*DMODEL];
__device__ __align__(16) __half g_x2  [MROWS*DMODEL];
__device__ __align__(16) __half g_x2d [MROWS*DMODEL];
__device__ __align__(16) __half g_qb  [MROWS*DMODEL];
__device__ __align__(16) __half g_ctx [MROWS*DMODEL];
__device__ __align__(16) __half g_ctxd[MROWS*DMODEL];
__device__ __align__(16) __half g_enc [MROWS*DMODEL];
__device__ __align__(16) __half g_h   [MROWS*DFF];
__device__ __align__(16) __half g_qkv [MROWS*3*DMODEL];
__device__ __align__(16) __half g_qkvd[MROWS*3*DMODEL];
__device__ __align__(16) __half g_kvb [NLAYER][MROWS*2*DMODEL];

// converted-weight arena (fp16)
#define OFF_ENC_ATTN 0
#define OFF_ENC_W1   (OFF_ENC_ATTN + NLAYER*4*DMODEL*DMODEL)
#define OFF_ENC_W2   (OFF_ENC_W1   + NLAYER*DFF*DMODEL)
#define OFF_DEC_ATTN (OFF_ENC_W2   + NLAYER*DMODEL*DFF)
#define OFF_DEC_W1   (OFF_DEC_ATTN + NLAYER*8*DMODEL*DMODEL)
#define OFF_DEC_W2   (OFF_DEC_W1   + NLAYER*DFF*DMODEL)
#define OFF_EMB      (OFF_DEC_W2   + NLAYER*DMODEL*DFF)
#define W_TOTAL      (OFF_EMB      + VOCAB*DMODEL)
__device__ __align__(16) __half g_w[W_TOTAL];

// ---------------------------------------------------------------------------
// fp32 -> fp16 conversion
// ---------------------------------------------------------------------------
__global__ void cvt_kernel(const float* __restrict__ in, __half* __restrict__ out, int n) {
    int i = (blockIdx.x*blockDim.x + threadIdx.x)*8;
    if (i < n) {
        float4 a = *(const float4*)(in + i);
        float4 b = *(const float4*)(in + i + 4);
        __half2 h0 = __floats2half2_rn(a.x, a.y);
        __half2 h1 = __floats2half2_rn(a.z, a.w);
        __half2 h2 = __floats2half2_rn(b.x, b.y);
        __half2 h3 = __floats2half2_rn(b.z, b.w);
        uint4 o;
        o.x = *(uint32_t*)&h0; o.y = *(uint32_t*)&h1;
        o.z = *(uint32_t*)&h2; o.w = *(uint32_t*)&h3;
        *(uint4*)(out + i) = o;
    }
}

// ---------------------------------------------------------------------------
// Embedding + sinusoidal positional encoding (residual stream, fp32)
// ---------------------------------------------------------------------------
__global__ void embed_kernel(const int* __restrict__ tok,
                             const float* __restrict__ emb,
                             float* __restrict__ y) {
    int row = blockIdx.x;
    int s   = row % SEQ;
    int t   = tok[row];
    const float scale = 22.62741699796952f;
    const float c0 = -9.210340371976184f / (float)DMODEL;
    int tid = threadIdx.x;
    #pragma unroll
    for (int i = 0; i < 4; i++) {
        int d = tid + i*128;
        float e = (t == 0) ? 0.f : emb[(size_t)t*DMODEL + d];
        int half = d >> 1;
        float div = expf((float)(2*half) * c0);
        float ang = (float)s * div;
        float pe = (d & 1) ? cosf(ang) : sinf(ang);
        y[(size_t)row*DMODEL + d] = e*scale + pe;
    }
}

// ---------------------------------------------------------------------------
// LayerNorm, warp-per-row (8 rows / 256-thread block).
// ---------------------------------------------------------------------------
__global__ __launch_bounds__(256)
void ln_kernel(const float* __restrict__ x,
               const float* __restrict__ g,
               const float* __restrict__ b,
               __half* __restrict__ y) {
    int row  = blockIdx.x*8 + (threadIdx.x >> 5);
    int lane = threadIdx.x & 31;
    const float* xr = x + (size_t)row*DMODEL;
    float4 v[4];
    float s = 0.f;
    #pragma unroll
    for (int c = 0; c < 4; c++) {
        v[c] = *(const float4*)(xr + lane*4 + c*128);
        s += (v[c].x + v[c].y) + (v[c].z + v[c].w);
    }
    #pragma unroll
    for (int o = 16; o > 0; o >>= 1) s += __shfl_xor_sync(0xffffffffu, s, o);
    float mean = s * (1.f/(float)DMODEL);
    float vs = 0.f;
    #pragma unroll
    for (int c = 0; c < 4; c++) {
        float d0 = v[c].x-mean, d1 = v[c].y-mean, d2 = v[c].z-mean, d3 = v[c].w-mean;
        vs += d0*d0 + d1*d1 + d2*d2 + d3*d3;
    }
    #pragma unroll
    for (int o = 16; o > 0; o >>= 1) vs += __shfl_xor_sync(0xffffffffu, vs, o);
    float inv = rsqrtf(vs * (1.f/(float)DMODEL) + 1e-5f);
    #pragma unroll
    for (int c = 0; c < 4; c++) {
        int d = lane*4 + c*128;
        float4 gv = *(const float4*)(g + d);
        float4 bv = *(const float4*)(b + d);
        float r0 = (v[c].x-mean)*inv*gv.x + bv.x;
        float r1 = (v[c].y-mean)*inv*gv.y + bv.y;
        float r2 = (v[c].z-mean)*inv*gv.z + bv.z;
        float r3 = (v[c].w-mean)*inv*gv.w + bv.w;
        __half2 h0 = __floats2half2_rn(r0, r1);
        __half2 h1 = __floats2half2_rn(r2, r3);
        uint2 o; o.x = *(uint32_t*)&h0; o.y = *(uint32_t*)&h1;
        *(uint2*)(y + (size_t)row*DMODEL + d) = o;
    }
}

// ---------------------------------------------------------------------------
// fp16 mma.sync GEMM, CTA 128x128x64 (wide-N shapes). BK=64: half the
// barriers/waits per CTA vs BK=32; stride 72 halfs (144B = 4 banks mod 32
// -> conflict-free ldmatrix phases, same arithmetic as attention's ASS=72).
// smem 3 x 36864B = 110592B -> still 2 CTA/SM.
// ---------------------------------------------------------------------------
#define T64 72
#define TILE64_HALFS (128*T64)            // 9216
#define STAGE64_HALFS (2*TILE64_HALFS)    // 18432
#define GEMM_SMEM (3*STAGE64_HALFS*2)     // 110592 bytes

template<bool RELU, bool RES, bool BIAS, bool OHALF>
__global__ __launch_bounds__(256, 2)
void gemm_mma(const __half* __restrict__ A, const __half* __restrict__ W,
              const float* __restrict__ bias, const float* __restrict__ res,
              void* __restrict__ Cv, int M, int N, int K) {
    extern __shared__ __half smh[];
    int t = threadIdx.x, lane = t & 31, wid = t >> 5;
    int wm = (wid & 1) * 64;
    int wn = (wid >> 1) * 32;
    int r4 = lane >> 2, l4 = lane & 3;

    const __half* Ab = A + (size_t)blockIdx.y*128*K;
    const __half* Wb = W + (size_t)blockIdx.x*128*K;
    uint32_t sbase = smem_u32(smh);

    float acc[4][4][4];
    #pragma unroll
    for (int i = 0; i < 4; i++)
        #pragma unroll
        for (int j = 0; j < 4; j++)
            #pragma unroll
            for (int c = 0; c < 4; c++) acc[i][j][c] = 0.f;

    int NK = K >> 6;

    auto issue = [&](int it, int buf) {
        uint32_t base = sbase + (uint32_t)buf*STAGE64_HALFS*2;
        int k0 = it*64;
        #pragma unroll
        for (int i = 0; i < 4; i++) {
            int idx = t + i*256, r = idx >> 3, ch = idx & 7;
            uint32_t off = (uint32_t)(r*T64 + ch*8)*2;
            cp16(base + off,                    Ab + (size_t)r*K + k0 + ch*8);
            cp16(base + TILE64_HALFS*2 + off,   Wb + (size_t)r*K + k0 + ch*8);
        }
        CP_COMMIT();
    };

    issue(0, 0);
    issue(1, 1);

    int a_row = (lane & 15);
    int a_kh8 = (lane >> 4) * 8;
    int b_row = (lane & 7) + ((lane >> 4) & 1) * 8;
    int b_kh8 = ((lane >> 3) & 1) * 8;

    for (int it = 0; it < NK; it++) {
        if (it + 1 < NK) cp_wait<1>(); else cp_wait<0>();
        __syncthreads();
        if (it + 2 < NK) issue(it + 2, (it + 2) % 3);
        uint32_t sA = sbase + (uint32_t)(it % 3)*STAGE64_HALFS*2;
        uint32_t sB = sA + TILE64_HALFS*2;
        #pragma unroll
        for (int kh = 0; kh < 4; kh++) {
            uint32_t af[4][4], bf[2][4];
            #pragma unroll
            for (int mi = 0; mi < 4; mi++)
                ldm_x4(af[mi], sA + (uint32_t)((wm + mi*16 + a_row)*T64 + kh*16 + a_kh8)*2);
            #pragma unroll
            for (int nb = 0; nb < 2; nb++)
                ldm_x4(bf[nb], sB + (uint32_t)((wn + nb*16 + b_row)*T64 + kh*16 + b_kh8)*2);
            #pragma unroll
            for (int mi = 0; mi < 4; mi++) {
                #pragma unroll
                for (int ni = 0; ni < 4; ni++)
                    mma_f16(acc[mi][ni], af[mi], bf[ni >> 1] + (ni & 1)*2);
            }
        }
    }

    int gm = blockIdx.y*128 + wm;
    int gn = blockIdx.x*128 + wn;
    #pragma unroll
    for (int mi = 0; mi < 4; mi++) {
        #pragma unroll
        for (int ni = 0; ni < 4; ni++) {
            int row = gm + mi*16 + r4;
            int col = gn + ni*8 + l4*2;
            float2 v0 = make_float2(acc[mi][ni][0], acc[mi][ni][1]);
            float2 v1 = make_float2(acc[mi][ni][2], acc[mi][ni][3]);
            if (BIAS) {
                float2 bv = *(const float2*)(bias + col);
                v0.x += bv.x; v0.y += bv.y; v1.x += bv.x; v1.y += bv.y;
            }
            if (RELU) {
                v0.x = fmaxf(v0.x, 0.f); v0.y = fmaxf(v0.y, 0.f);
                v1.x = fmaxf(v1.x, 0.f); v1.y = fmaxf(v1.y, 0.f);
            }
            if (RES) {
                float2 r0 = *(const float2*)(res + (size_t)row*N + col);
                float2 r1 = *(const float2*)(res + (size_t)(row+8)*N + col);
                v0.x += r0.x; v0.y += r0.y; v1.x += r1.x; v1.y += r1.y;
            }
            if (OHALF) {
                __half* C = (__half*)Cv;
                *(__half2*)(C + (size_t)row*N + col)     = __floats2half2_rn(v0.x, v0.y);
                *(__half2*)(C + (size_t)(row+8)*N + col) = __floats2half2_rn(v1.x, v1.y);
            } else {
                float* C = (float*)Cv;
                *(float2*)(C + (size_t)row*N + col)     = v0;
                *(float2*)(C + (size_t)(row+8)*N + col) = v1;
            }
        }
    }
}

// ---------------------------------------------------------------------------
// fp16 mma.sync GEMM, CTA 64x128x32 (narrow-N shapes). (unchanged)
// ---------------------------------------------------------------------------
#define TSTR 40
#define TILE_HALFS (128*TSTR)
#define A64_HALFS (64*TSTR)
#define S64_HALFS (A64_HALFS + TILE_HALFS)
#define GEMM64_SMEM (3*S64_HALFS*2)

template<bool RELU, bool RES, bool BIAS, bool OHALF>
__global__ __launch_bounds__(256)
void gemm_mma64(const __half* __restrict__ A, const __half* __restrict__ W,
                const float* __restrict__ bias, const float* __restrict__ res,
                void* __restrict__ Cv, int M, int N, int K) {
    extern __shared__ __half smh[];
    int t = threadIdx.x, lane = t & 31, wid = t >> 5;
    int wm = (wid & 1) * 32;
    int wn = (wid >> 1) * 32;
    int r4 = lane >> 2, l4 = lane & 3;

    const __half* Ab = A + (size_t)blockIdx.y*64*K;
    const __half* Wb = W + (size_t)blockIdx.x*128*K;
    uint32_t sbase = smem_u32(smh);

    float acc[2][4][4];
    #pragma unroll
    for (int i = 0; i < 2; i++)
        #pragma unroll
        for (int j = 0; j < 4; j++)
            #pragma unroll
            for (int c = 0; c < 4; c++) acc[i][j][c] = 0.f;

    int NK = K >> 5;

    auto issue = [&](int it, int buf) {
        uint32_t base = sbase + (uint32_t)buf*S64_HALFS*2;
        int k0 = it*32;
        {
            int r = t >> 2, ch = t & 3;
            cp16(base + (uint32_t)(r*TSTR + ch*8)*2, Ab + (size_t)r*K + k0 + ch*8);
        }
        #pragma unroll
        for (int i = 0; i < 2; i++) {
            int idx = t + i*256, r = idx >> 2, ch = idx & 3;
            cp16(base + A64_HALFS*2 + (uint32_t)(r*TSTR + ch*8)*2,
                 Wb + (size_t)r*K + k0 + ch*8);
        }
        CP_COMMIT();
    };

    issue(0, 0);
    issue(1, 1);

    int a_row = (lane & 15);
    int a_kh8 = (lane >> 4) * 8;
    int b_row = (lane & 7) + ((lane >> 4) & 1) * 8;
    int b_kh8 = ((lane >> 3) & 1) * 8;

    for (int it = 0; it < NK; it++) {
        if (it + 1 < NK) cp_wait<1>(); else cp_wait<0>();
        __syncthreads();
        if (it + 2 < NK) issue(it + 2, (it + 2) % 3);
        uint32_t sA = sbase + (uint32_t)(it % 3)*S64_HALFS*2;
        uint32_t sB = sA + A64_HALFS*2;
        #pragma unroll
        for (int kh = 0; kh < 2; kh++) {
            uint32_t af[2][4], bf[2][4];
            #pragma unroll
            for (int mi = 0; mi < 2; mi++)
                ldm_x4(af[mi], sA + (uint32_t)((wm + mi*16 + a_row)*TSTR + kh*16 + a_kh8)*2);
            #pragma unroll
            for (int nb = 0; nb < 2; nb++)
                ldm_x4(bf[nb], sB + (uint32_t)((wn + nb*16 + b_row)*TSTR + kh*16 + b_kh8)*2);
            #pragma unroll
            for (int mi = 0; mi < 2; mi++) {
                #pragma unroll
                for (int ni = 0; ni < 4; ni++)
                    mma_f16(acc[mi][ni], af[mi], bf[ni >> 1] + (ni & 1)*2);
            }
        }
    }

    int gm = blockIdx.y*64 + wm;
    int gn = blockIdx.x*128 + wn;
    #pragma unroll
    for (int mi = 0; mi < 2; mi++) {
        #pragma unroll
        for (int ni = 0; ni < 4; ni++) {
            int row = gm + mi*16 + r4;
            int col = gn + ni*8 + l4*2;
            float2 v0 = make_float2(acc[mi][ni][0], acc[mi][ni][1]);
            float2 v1 = make_float2(acc[mi][ni][2], acc[mi][ni][3]);
            if (BIAS) {
                float2 bv = *(const float2*)(bias + col);
                v0.x += bv.x; v0.y += bv.y; v1.x += bv.x; v1.y += bv.y;
            }
            if (RELU) {
                v0.x = fmaxf(v0.x, 0.f); v0.y = fmaxf(v0.y, 0.f);
                v1.x = fmaxf(v1.x, 0.f); v1.y = fmaxf(v1.y, 0.f);
            }
            if (RES) {
                float2 r0 = *(const float2*)(res + (size_t)row*N + col);
                float2 r1 = *(const float2*)(res + (size_t)(row+8)*N + col);
                v0.x += r0.x; v0.y += r0.y; v1.x += r1.x; v1.y += r1.y;
            }
            if (OHALF) {
                __half* C = (__half*)Cv;
                *(__half2*)(C + (size_t)row*N + col)     = __floats2half2_rn(v0.x, v0.y);
                *(__half2*)(C + (size_t)(row+8)*N + col) = __floats2half2_rn(v1.x, v1.y);
            } else {
                float* C = (float*)Cv;
                *(float2*)(C + (size_t)row*N + col)     = v0;
                *(float2*)(C + (size_t)(row+8)*N + col) = v1;
            }
        }
    }
}

// ---------------------------------------------------------------------------
// Flash attention, fp16 inputs, cp.async double-buffered K/V. (R10 exact)
// ---------------------------------------------------------------------------
#define ASS 72
#define ATILE (64*ASS)
#define FH_TOT (6*ATILE)
#define ATTN_SMEM (FH_TOT*2 + 2816)

__global__ __launch_bounds__(128)
void attn_mma(const __half* __restrict__ Qp, int qstride,
              const __half* __restrict__ Kp, const __half* __restrict__ Vp, int kvstride,
              __half* __restrict__ Op,
              const int* __restrict__ mtok, int causal) {
    extern __shared__ __half smh[];
    __half* Ps = smh + 5*ATILE;
    float* alphas = (float*)(smh + FH_TOT);
    float* linv   = alphas + 64;
    uint32_t* maskv = (uint32_t*)(linv + 64);

    int t = threadIdx.x, lane = t & 31, w = t >> 5;
    int r4 = lane >> 2, l4 = lane & 3;
    int q0 = blockIdx.x * 64, h = blockIdx.y, b = blockIdx.z;
    const __half* Qb = Qp + (size_t)b*SEQ*qstride  + h*DHEAD;
    const __half* Kb = Kp + (size_t)b*SEQ*kvstride + h*DHEAD;
    const __half* Vb = Vp + (size_t)b*SEQ*kvstride + h*DHEAD;

    uint32_t qs_b = smem_u32(smh);
    uint32_t ps_b = smem_u32(Ps);

    int a_row = (lane & 15);
    int a_k8  = (lane >> 4) * 8;
    int b_row = (lane & 7) + ((lane >> 4) & 1) * 8;
    int b_k8  = ((lane >> 3) & 1) * 8;
    int v_s   = (lane & 7) + ((lane >> 4) & 1) * 8;
    int v_d8  = ((lane >> 3) & 1) * 8;

    int qcnk = q0 >> 6;
    int nchunks = causal ? (qcnk + 1) : (SEQ/64);

    auto issue_kv = [&](int kt, int buf) {
        uint32_t kbase = qs_b + (uint32_t)(1 + buf)*ATILE*2;
        uint32_t vbase = qs_b + (uint32_t)(3 + buf)*ATILE*2;
        const __half* Kc = Kb + (size_t)kt*64*kvstride;
        const __half* Vc = Vb + (size_t)kt*64*kvstride;
        #pragma unroll
        for (int i = 0; i < 4; i++) {
            int idx = t + i*128, s = idx >> 3, ch = idx & 7;
            uint32_t off = (uint32_t)(s*ASS + ch*8)*2;
            cp16(kbase + off, Kc + (size_t)s*kvstride + ch*8);
            cp16(vbase + off, Vc + (size_t)s*kvstride + ch*8);
        }
        CP_COMMIT();
    };

    #pragma unroll
    for (int i = 0; i < 4; i++) {
        int idx = t + i*128, s = idx >> 3, ch = idx & 7;
        cp16(qs_b + (uint32_t)(s*ASS + ch*8)*2, Qb + (size_t)(q0+s)*qstride + ch*8);
    }
    CP_COMMIT();
    #pragma unroll
    for (int i = 0; i < 4; i++) {
        int idx = t + i*128;
        maskv[idx] = (mtok[b*SEQ + idx] != 0);
    }
    issue_kv(0, 0);
    cp_wait<1>();
    __syncthreads();

    int m0 = w*16;
    uint32_t qf[4][4];
    #pragma unroll
    for (int kh = 0; kh < 4; kh++)
        ldm_x4(qf[kh], qs_b + (uint32_t)((m0 + a_row)*ASS + kh*16 + a_k8)*2);

    float oacc[8][4];
    #pragma unroll
    for (int j = 0; j < 8; j++)
        #pragma unroll
        for (int c = 0; c < 4; c++) oacc[j][c] = 0.f;
    float mrA = -1e30f, mrB = -1e30f, lrA = 0.f, lrB = 0.f;
    int qA = q0 + m0 + r4, qB = qA + 8;

    for (int kt = 0; kt < nchunks; kt++) {
        cp_wait<0>();
        __syncthreads();
        if (kt + 1 < nchunks) issue_kv(kt + 1, (kt + 1) & 1);
        uint32_t ks_b = qs_b + (uint32_t)(1 + (kt & 1))*ATILE*2;
        uint32_t vs_b = qs_b + (uint32_t)(3 + (kt & 1))*ATILE*2;

        float sacc[8][4];
        #pragma unroll
        for (int j = 0; j < 8; j++)
            #pragma unroll
            for (int c = 0; c < 4; c++) sacc[j][c] = 0.f;
        #pragma unroll
        for (int kh = 0; kh < 4; kh++) {
            uint32_t bf[4][4];
            #pragma unroll
            for (int nb = 0; nb < 4; nb++)
                ldm_x4(bf[nb], ks_b + (uint32_t)((nb*16 + b_row)*ASS + kh*16 + b_k8)*2);
            #pragma unroll
            for (int nb = 0; nb < 4; nb++) {
                mma_f16(sacc[nb*2],     qf[kh], bf[nb]);
                mma_f16(sacc[nb*2 + 1], qf[kh], bf[nb] + 2);
            }
        }
        bool diag = causal && (kt == qcnk);
        float mA = -1e30f, mB = -1e30f;
        #pragma unroll
        for (int j = 0; j < 8; j++) {
            int kl = j*8 + 2*l4;
            int kg = kt*64 + kl;
            bool pv0 = maskv[kg] != 0, pv1 = maskv[kg+1] != 0;
            bool a0 = pv0 && (!diag || kg   <= qA);
            bool a1 = pv1 && (!diag || kg+1 <= qA);
            bool b0 = pv0 && (!diag || kg   <= qB);
            bool b1 = pv1 && (!diag || kg+1 <= qB);
            sacc[j][0] = a0 ? sacc[j][0]*0.125f : -1e9f;
            sacc[j][1] = a1 ? sacc[j][1]*0.125f : -1e9f;
            sacc[j][2] = b0 ? sacc[j][2]*0.125f : -1e9f;
            sacc[j][3] = b1 ? sacc[j][3]*0.125f : -1e9f;
            mA = fmaxf(mA, fmaxf(sacc[j][0], sacc[j][1]));
            mB = fmaxf(mB, fmaxf(sacc[j][2], sacc[j][3]));
        }
        mA = fmaxf(mA, __shfl_xor_sync(0xffffffffu, mA, 1));
        mA = fmaxf(mA, __shfl_xor_sync(0xffffffffu, mA, 2));
        mB = fmaxf(mB, __shfl_xor_sync(0xffffffffu, mB, 1));
        mB = fmaxf(mB, __shfl_xor_sync(0xffffffffu, mB, 2));
        float mnA = fmaxf(mrA, mA), mnB = fmaxf(mrB, mB);
        float aA = __expf(mrA - mnA), aB = __expf(mrB - mnB);
        mrA = mnA; mrB = mnB;
        float lA = 0.f, lB = 0.f;
        #pragma unroll
        for (int j = 0; j < 8; j++) {
            float p0 = __expf(sacc[j][0] - mnA);
            float p1 = __expf(sacc[j][1] - mnA);
            float p2 = __expf(sacc[j][2] - mnB);
            float p3 = __expf(sacc[j][3] - mnB);
            lA += p0 + p1; lB += p2 + p3;
            *(__half2*)(Ps + (m0 + r4)*ASS     + j*8 + 2*l4) = __floats2half2_rn(p0, p1);
            *(__half2*)(Ps + (m0 + r4 + 8)*ASS + j*8 + 2*l4) = __floats2half2_rn(p2, p3);
        }
        lA += __shfl_xor_sync(0xffffffffu, lA, 1);
        lA += __shfl_xor_sync(0xffffffffu, lA, 2);
        lB += __shfl_xor_sync(0xffffffffu, lB, 1);
        lB += __shfl_xor_sync(0xffffffffu, lB, 2);
        lrA = lrA*aA + lA;
        lrB = lrB*aB + lB;
        if (l4 == 0) {
            alphas[m0 + r4]     = aA;
            alphas[m0 + r4 + 8] = aB;
            if (kt == nchunks - 1) {
                linv[m0 + r4]     = 1.f / lrA;
                linv[m0 + r4 + 8] = 1.f / lrB;
            }
        }
        __syncthreads();

        #pragma unroll
        for (int j = 0; j < 8; j++) {
            float a0 = alphas[j*8 + 2*l4];
            float a1 = alphas[j*8 + 2*l4 + 1];
            oacc[j][0] *= a0; oacc[j][1] *= a1;
            oacc[j][2] *= a0; oacc[j][3] *= a1;
        }
        #pragma unroll
        for (int kh = 0; kh < 4; kh++) {
            uint32_t af[4];
            ldm_x4_t(af, vs_b + (uint32_t)((kh*16 + v_s)*ASS + m0 + v_d8)*2);
            #pragma unroll
            for (int jb = 0; jb < 4; jb++) {
                uint32_t bf[4];
                ldm_x4(bf, ps_b + (uint32_t)((jb*16 + b_row)*ASS + kh*16 + b_k8)*2);
                mma_f16(oacc[jb*2],     af, bf);
                mma_f16(oacc[jb*2 + 1], af, bf + 2);
            }
        }
    }

    #pragma unroll
    for (int j = 0; j < 8; j++) {
        int qc2 = j*8 + 2*l4;
        float i0 = linv[qc2], i1 = linv[qc2 + 1];
        int d0 = m0 + r4;
        size_t ro0 = ((size_t)b*SEQ + q0 + qc2)*DMODEL + h*DHEAD;
        size_t ro1 = ro0 + DMODEL;
        Op[ro0 + d0]     = __float2half_rn(oacc[j][0]*i0);
        Op[ro1 + d0]     = __float2half_rn(oacc[j][1]*i1);
        Op[ro0 + d0 + 8] = __float2half_rn(oacc[j][2]*i0);
        Op[ro1 + d0 + 8] = __float2half_rn(oacc[j][3]*i1);
    }
}

// ---------------------------------------------------------------------------
// Host-side stream/event resources (static-init, pre-checkpoint).
// ---------------------------------------------------------------------------
struct StreamCtx {
    cudaStream_t s1 = nullptr;
    cudaEvent_t root = nullptr, enc = nullptr, dec0 = nullptr, kv[NLAYER] = {};
    bool ok = false;
    StreamCtx() {
        if (cudaStreamCreateWithFlags(&s1, cudaStreamNonBlocking) != cudaSuccess) return;
        if (cudaEventCreateWithFlags(&root, cudaEventDisableTiming) != cudaSuccess) return;
        if (cudaEventCreateWithFlags(&enc,  cudaEventDisableTiming) != cudaSuccess) return;
        if (cudaEventCreateWithFlags(&dec0, cudaEventDisableTiming) != cudaSuccess) return;
        for (int i = 0; i < NLAYER; i++)
            if (cudaEventCreateWithFlags(&kv[i], cudaEventDisableTiming) != cudaSuccess) return;
        ok = true;
    }
};
static StreamCtx g_sc;

// ---------------------------------------------------------------------------
// Orchestration
// ---------------------------------------------------------------------------
static inline void launch_gemm(const __half* A, const __half* W, const float* bias,
                               const float* res, void* C, int M, int N, int K,
                               bool relu, cudaStream_t st) {
    if (N <= 1024) {
        dim3 grid(N/128, M/64), block(256);
        if (res)        gemm_mma64<false,true ,true ,false><<<grid, block, GEMM64_SMEM, st>>>(A, W, bias, res, C, M, N, K);
        else if (relu)  gemm_mma64<true ,false,true ,true ><<<grid, block, GEMM64_SMEM, st>>>(A, W, bias, nullptr, C, M, N, K);
        else if (bias)  gemm_mma64<false,false,true ,true ><<<grid, block, GEMM64_SMEM, st>>>(A, W, bias, nullptr, C, M, N, K);
        else            gemm_mma64<false,false,false,false><<<grid, block, GEMM64_SMEM, st>>>(A, W, nullptr, nullptr, C, M, N, K);
        return;
    }
    dim3 grid(N/128, M/128), block(256);
    if (res)        gemm_mma<false,true ,true ,false><<<grid, block, GEMM_SMEM, st>>>(A, W, bias, res, C, M, N, K);
    else if (relu)  gemm_mma<true ,false,true ,true ><<<grid, block, GEMM_SMEM, st>>>(A, W, bias, nullptr, C, M, N, K);
    else if (bias)  gemm_mma<false,false,true ,true ><<<grid, block, GEMM_SMEM, st>>>(A, W, bias, nullptr, C, M, N, K);
    else            gemm_mma<false,false,false,false><<<grid, block, GEMM_SMEM, st>>>(A, W, nullptr, nullptr, C, M, N, K);
}

extern "C" void kernel_launch(void* const* d_in, const int* in_sizes, int n_in,
                              void* d_out, int out_size) {
    const int*   src        = (const int*)  d_in[0];
    const int*   tgt        = (const int*)  d_in[1];
    const float* emb        = (const float*)d_in[2];
    const float* enc_attn_w = (const float*)d_in[3];
    const float* enc_attn_b = (const float*)d_in[4];
    const float* enc_ln_g   = (const float*)d_in[5];
    const float* enc_ln_b   = (const float*)d_in[6];
    const float* enc_w1     = (const float*)d_in[7];
    const float* enc_b1     = (const float*)d_in[8];
    const float* enc_w2     = (const float*)d_in[9];
    const float* enc_b2     = (const float*)d_in[10];
    const float* dec_attn_w = (const float*)d_in[11];
    const float* dec_attn_b = (const float*)d_in[12];
    const float* dec_ln_g   = (const float*)d_in[13];
    const float* dec_ln_b   = (const float*)d_in[14];
    const float* dec_w1     = (const float*)d_in[15];
    const float* dec_b1     = (const float*)d_in[16];
    const float* dec_w2     = (const float*)d_in[17];
    const float* dec_b2     = (const float*)d_in[18];
    const float* enc_norm_g = (const float*)d_in[19];
    const float* enc_norm_b = (const float*)d_in[20];
    const float* dec_norm_g = (const float*)d_in[21];
    const float* dec_norm_b = (const float*)d_in[22];

    float *x, *xd;
    __half *x2, *x2d, *qb, *ctx, *ctxd, *enc, *hbuf, *qkv, *qkvd, *wv;
    __half *kvb[NLAYER];
    cudaGetSymbolAddress((void**)&x,    g_x);
    cudaGetSymbolAddress((void**)&xd,   g_xd);
    cudaGetSymbolAddress((void**)&x2,   g_x2);
    cudaGetSymbolAddress((void**)&x2d,  g_x2d);
    cudaGetSymbolAddress((void**)&qb,   g_qb);
    cudaGetSymbolAddress((void**)&ctx,  g_ctx);
    cudaGetSymbolAddress((void**)&ctxd, g_ctxd);
    cudaGetSymbolAddress((void**)&enc,  g_enc);
    cudaGetSymbolAddress((void**)&hbuf, g_h);
    cudaGetSymbolAddress((void**)&qkv,  g_qkv);
    cudaGetSymbolAddress((void**)&qkvd, g_qkvd);
    cudaGetSymbolAddress((void**)&wv,   g_w);
    {
        __half* kvb0;
        cudaGetSymbolAddress((void**)&kvb0, g_kvb);
        for (int l = 0; l < NLAYER; l++) kvb[l] = kvb0 + (size_t)l*MROWS*2*DMODEL;
    }

    cudaFuncSetAttribute(attn_mma, cudaFuncAttributeMaxDynamicSharedMemorySize, ATTN_SMEM);
    cudaFuncSetAttribute(gemm_mma<false,true ,true ,false>, cudaFuncAttributeMaxDynamicSharedMemorySize, GEMM_SMEM);
    cudaFuncSetAttribute(gemm_mma<true ,false,true ,true >, cudaFuncAttributeMaxDynamicSharedMemorySize, GEMM_SMEM);
    cudaFuncSetAttribute(gemm_mma<false,false,true ,true >, cudaFuncAttributeMaxDynamicSharedMemorySize, GEMM_SMEM);
    cudaFuncSetAttribute(gemm_mma<false,false,false,false>, cudaFuncAttributeMaxDynamicSharedMemorySize, GEMM_SMEM);
    cudaFuncSetAttribute(gemm_mma64<false,true ,true ,false>, cudaFuncAttributeMaxDynamicSharedMemorySize, GEMM64_SMEM);
    cudaFuncSetAttribute(gemm_mma64<true ,false,true ,true >, cudaFuncAttributeMaxDynamicSharedMemorySize, GEMM64_SMEM);
    cudaFuncSetAttribute(gemm_mma64<false,false,true ,true >, cudaFuncAttributeMaxDynamicSharedMemorySize, GEMM64_SMEM);
    cudaFuncSetAttribute(gemm_mma64<false,false,false,false>, cudaFuncAttributeMaxDynamicSharedMemorySize, GEMM64_SMEM);

    const int D = DMODEL, M = MROWS;
    const size_t WSZ = (size_t)D*D;
    dim3 attnGrid(SEQ/64, NHEAD, BATCH);
    const __half* ew = wv + OFF_ENC_ATTN;
    const __half* dw = wv + OFF_DEC_ATTN;

    const bool par = g_sc.ok;
    cudaStream_t s0 = 0;
    cudaStream_t s1 = par ? g_sc.s1 : (cudaStream_t)0;

    if (par) {
        cudaEventRecord(g_sc.root, s0);
        cudaStreamWaitEvent(s1, g_sc.root, 0);
    }

    // ----- s1: decoder-side cvt + embed + layer-0 self-attn block -----
    cvt_kernel<<<(NLAYER*8*DMODEL*DMODEL)/2048, 256, 0, s1>>>(dec_attn_w, wv + OFF_DEC_ATTN, NLAYER*8*DMODEL*DMODEL);
    cvt_kernel<<<(NLAYER*DFF*DMODEL)/2048,      256, 0, s1>>>(dec_w1,     wv + OFF_DEC_W1,   NLAYER*DFF*DMODEL);
    cvt_kernel<<<(NLAYER*DMODEL*DFF)/2048,      256, 0, s1>>>(dec_w2,     wv + OFF_DEC_W2,   NLAYER*DMODEL*DFF);
    cvt_kernel<<<(VOCAB*DMODEL)/2048,           256, 0, s1>>>(emb,        wv + OFF_EMB,      VOCAB*DMODEL);
    embed_kernel<<<M, 128, 0, s1>>>(tgt, emb, xd);
    {
        const __half* w  = dw;
        const float*  bb = dec_attn_b;
        ln_kernel<<<M/8, 256, 0, s1>>>(xd, dec_ln_g, dec_ln_b, x2d);
        launch_gemm(x2d, w, bb, nullptr, qkvd, M, 3*D, D, false, s1);
        attn_mma<<<attnGrid, 128, ATTN_SMEM, s1>>>(qkvd, 3*D, qkvd + D, qkvd + 2*D, 3*D, ctxd, tgt, 1);
        launch_gemm(ctxd, w + 3*WSZ, bb + 3*D, xd, xd, M, D, D, false, s1);
        ln_kernel<<<M/8, 256, 0, s1>>>(xd, dec_ln_g + (size_t)1*D, dec_ln_b + (size_t)1*D, x2d);
    }
    if (par) cudaEventRecord(g_sc.dec0, s1);

    // ----- s0: encoder-side cvt + embed + encoder -----
    cvt_kernel<<<(NLAYER*4*DMODEL*DMODEL)/2048, 256, 0, s0>>>(enc_attn_w, wv + OFF_ENC_ATTN, NLAYER*4*DMODEL*DMODEL);
    cvt_kernel<<<(NLAYER*DFF*DMODEL)/2048,      256, 0, s0>>>(enc_w1,     wv + OFF_ENC_W1,   NLAYER*DFF*DMODEL);
    cvt_kernel<<<(NLAYER*DMODEL*DFF)/2048,      256, 0, s0>>>(enc_w2,     wv + OFF_ENC_W2,   NLAYER*DMODEL*DFF);
    embed_kernel<<<M, 128, 0, s0>>>(src, emb, x);
    for (int l = 0; l < NLAYER; l++) {
        const __half* w  = ew + (size_t)l*4*WSZ;
        const float*  bb = enc_attn_b + (size_t)l*4*D;
        ln_kernel<<<M/8, 256, 0, s0>>>(x, enc_ln_g + (size_t)(l*2+0)*D, enc_ln_b + (size_t)(l*2+0)*D, x2);
        launch_gemm(x2, w, bb, nullptr, qkv, M, 3*D, D, false, s0);
        attn_mma<<<attnGrid, 128, ATTN_SMEM, s0>>>(qkv, 3*D, qkv + D, qkv + 2*D, 3*D, ctx, src, 0);
        launch_gemm(ctx, w + 3*WSZ, bb + 3*D, x, x, M, D, D, false, s0);
        ln_kernel<<<M/8, 256, 0, s0>>>(x, enc_ln_g + (size_t)(l*2+1)*D, enc_ln_b + (size_t)(l*2+1)*D, x2);
        launch_gemm(x2, wv + OFF_ENC_W1 + (size_t)l*DFF*D, enc_b1 + (size_t)l*DFF, nullptr, hbuf, M, DFF, D, true, s0);
        launch_gemm(hbuf, wv + OFF_ENC_W2 + (size_t)l*D*DFF, enc_b2 + (size_t)l*D, x, x, M, D, DFF, false, s0);
    }
    ln_kernel<<<M/8, 256, 0, s0>>>(x, enc_norm_g, enc_norm_b, enc);
    if (par) cudaEventRecord(g_sc.enc, s0);

    // ----- s1: cross-KV projections (need enc) -----
    if (par) cudaStreamWaitEvent(s1, g_sc.enc, 0);
    for (int l = 0; l < NLAYER; l++) {
        const __half* w  = dw + (size_t)l*8*WSZ;
        const float*  bb = dec_attn_b + (size_t)l*8*D;
        launch_gemm(enc, w + 5*WSZ, bb + 5*D, nullptr, kvb[l], M, 2*D, D, false, s1);
        if (par) cudaEventRecord(g_sc.kv[l], s1);
    }

    // ----- s0: decoder -----
    if (par) cudaStreamWaitEvent(s0, g_sc.dec0, 0);
    for (int l = 0; l < NLAYER; l++) {
        const __half* w  = dw + (size_t)l*8*WSZ;
        const float*  bb = dec_attn_b + (size_t)l*8*D;
        if (l > 0) {
            ln_kernel<<<M/8, 256, 0, s0>>>(xd, dec_ln_g + (size_t)(l*3+0)*D, dec_ln_b + (size_t)(l*3+0)*D, x2d);
            launch_gemm(x2d, w, bb, nullptr, qkvd, M, 3*D, D, false, s0);
            attn_mma<<<attnGrid, 128, ATTN_SMEM, s0>>>(qkvd, 3*D, qkvd + D, qkvd + 2*D, 3*D, ctxd, tgt, 1);
            launch_gemm(ctxd, w + 3*WSZ, bb + 3*D, xd, xd, M, D, D, false, s0);
            ln_kernel<<<M/8, 256, 0, s0>>>(xd, dec_ln_g + (size_t)(l*3+1)*D, dec_ln_b + (size_t)(l*3+1)*D, x2d);
        }
        launch_gemm(x2d, w + 4*WSZ, bb + 4*D, nullptr, qb, M, D, D, false, s0);
        if (par) cudaStreamWaitEvent(s0, g_sc.kv[l], 0);
        attn_mma<<<attnGrid, 128, ATTN_SMEM, s0>>>(qb, D, kvb[l], kvb[l] + D, 2*D, ctxd, src, 0);
        launch_gemm(ctxd, w + 7*WSZ, bb + 7*D, xd, xd, M, D, D, false, s0);
        ln_kernel<<<M/8, 256, 0, s0>>>(xd, dec_ln_g + (size_t)(l*3+2)*D, dec_ln_b + (size_t)(l*3+2)*D, x2d);
        launch_gemm(x2d, wv + OFF_DEC_W1 + (size_t)l*DFF*D, dec_b1 + (size_t)l*DFF, nullptr, hbuf, M, DFF, D, true, s0);
        launch_gemm(hbuf, wv + OFF_DEC_W2 + (size_t)l*D*DFF, dec_b2 + (size_t)l*D, xd, xd, M, D, DFF, false, s0);
    }
    ln_kernel<<<M/8, 256, 0, s0>>>(xd, dec_norm_g, dec_norm_b, x2d);

    // ----- tied output projection -----
    launch_gemm(x2d, wv + OFF_EMB, nullptr, nullptr, (float*)d_out, M, VOCAB, D, false, s0);
}